// round 2
// baseline (speedup 1.0000x reference)
#include <cuda_runtime.h>

// ---------------------------------------------------------------------------
// ResidualGNNLayer: edge bucket -> warp-per-node aggregate -> feat[N,272]
//   -> GEMM1 (272x512, relu, f32x2 FMA) -> GEMM2 (512x128) + residual + LN
// ---------------------------------------------------------------------------

#define DD 128
#define HH 512
#define KF 258          // true feat width
#define KP 272          // padded feat width (17 * 16)
#define CAP 128         // max neighbors per node bucket (Poisson(12.8), max~40)
#define NN_MAX 50048    // 782 * 64

static __device__ int   g_is64;
static __device__ int   g_cnt[NN_MAX];
static __device__ float g_dist[NN_MAX];
static __device__ int   g_slots[NN_MAX * CAP];                 // 25.6 MB
static __device__ float g_feat[NN_MAX * KP];                   // 54.4 MB (zero-init; pad rows stay 0)
static __device__ float g_h[(size_t)NN_MAX * HH];              // 102.5 MB
static __device__ float g_W1p[KP * HH];                        // 557 KB

// ---- packed f32x2 helpers (Blackwell FFMA2) -------------------------------
__device__ __forceinline__ void fma2(unsigned long long& d, unsigned long long a,
                                     unsigned long long b) {
    asm("fma.rn.f32x2 %0, %1, %2, %0;" : "+l"(d) : "l"(a), "l"(b));
}
__device__ __forceinline__ unsigned long long pack2(float x, float y) {
    unsigned long long r;
    asm("mov.b64 %0, {%1, %2};" : "=l"(r) : "f"(x), "f"(y));
    return r;
}
__device__ __forceinline__ float2 unpack2(unsigned long long v) {
    float2 f;
    asm("mov.b64 {%0, %1}, %2;" : "=f"(f.x), "=f"(f.y) : "l"(v));
    return f;
}

// ---------------------------------------------------------------------------
// Detect whether edge_index arrived as int64 or int32.
// Sample only the first E int64-words: safe even if the buffer is int32
// (2E int32 = E int64 words). True int64 data -> sampled values in [0, Nn).
// int32 data viewed as int64 packs two random ids -> huge values.
__global__ void k_detect(const void* __restrict__ eraw, int E, int Nn) {
    if (blockIdx.x == 0 && threadIdx.x == 0) {
        const long long* p64 = (const long long*)eraw;
        int ok64 = 1;
        int step = E / 32;
        if (step < 1) step = 1;
        for (int i = 0; i < 32; i++) {
            long long idx = (long long)i * step;
            if (idx >= E) break;
            long long v = p64[idx];
            if (v < 0 || v >= Nn) { ok64 = 0; break; }
        }
        g_is64 = ok64;
    }
}

__global__ void k_zero(int Nn) {
    int i = blockIdx.x * blockDim.x + threadIdx.x;
    if (i < Nn) { g_cnt[i] = 0; g_dist[i] = 0.f; }
}

__global__ void k_padW1(const float* __restrict__ W1) {
    int i = blockIdx.x * blockDim.x + threadIdx.x;
    if (i < KP * HH) g_W1p[i] = (i < KF * HH) ? W1[i] : 0.f;
}

// bucket edges by src; accumulate dist per src
__global__ void k_edge(const void* __restrict__ eraw,
                       const float* __restrict__ ed, int E, int Nn) {
    int e = blockIdx.x * blockDim.x + threadIdx.x;
    if (e >= E) return;
    int src, dst;
    if (g_is64) {
        const long long* p = (const long long*)eraw;
        src = (int)p[e];
        dst = (int)p[E + e];
    } else {
        const int* p = (const int*)eraw;
        src = p[e];
        dst = p[E + e];
    }
    src = min(max(src, 0), Nn - 1);
    dst = min(max(dst, 0), Nn - 1);
    int p = atomicAdd(&g_cnt[src], 1);
    if (p < CAP) g_slots[src * CAP + p] = dst;
    atomicAdd(&g_dist[src], ed[e]);
}

// warp per node: gather + mean, build feat row [x | agg | deg | mean_dist | 0pad]
__global__ void k_feat(const float* __restrict__ x,
                       const float* __restrict__ degrees, int Nn) {
    int gw = (blockIdx.x * blockDim.x + threadIdx.x) >> 5;
    int lane = threadIdx.x & 31;
    if (gw >= Nn) return;
    int cnt = g_cnt[gw];
    if (cnt > CAP) cnt = CAP;
    const int* slots = g_slots + gw * CAP;
    float4 acc = make_float4(0.f, 0.f, 0.f, 0.f);
    int j = 0;
    int dnext = (cnt > 0) ? slots[0] : 0;
    for (; j < cnt; j++) {
        int dcur = dnext;
        if (j + 1 < cnt) dnext = slots[j + 1];
        float4 v = *(const float4*)(x + (size_t)dcur * DD + lane * 4);
        acc.x += v.x; acc.y += v.y; acc.z += v.z; acc.w += v.w;
    }
    float degRaw = degrees[gw];
    float deg = fmaxf(degRaw, 1.f);
    float inv = 1.f / deg;
    float* f = g_feat + gw * KP;
    float4 xv = *(const float4*)(x + (size_t)gw * DD + lane * 4);
    *(float4*)(f + lane * 4) = xv;
    *(float4*)(f + DD + lane * 4) =
        make_float4(acc.x * inv, acc.y * inv, acc.z * inv, acc.w * inv);
    if (lane < 16) {
        float v = 0.f;
        if (lane == 0) v = degRaw;
        else if (lane == 1) v = g_dist[gw] * inv;
        f[2 * DD + lane] = v;   // cols 256..271 (258..271 are zero pad)
    }
}

// ---------------------------------------------------------------------------
// GEMM1: h[N,512] = relu(feat[N,272] @ W1p[272,512] + b1)
// block: 64 rows x 128 cols, BK=16, 256 threads, thread tile 4x8 (f32x2 pairs)
// ---------------------------------------------------------------------------
__global__ __launch_bounds__(256) void k_gemm1(const float* __restrict__ b1) {
    __shared__ __align__(16) float sA[16][68];   // [k][row]
    __shared__ __align__(16) float sB[16][128];  // [k][col]
    int t = threadIdx.x;
    int row0 = blockIdx.x * 64;
    int col0 = blockIdx.y * 128;
    int arow = t >> 2, ac4 = (t & 3) * 4;
    int bk = t >> 5, bc4 = (t & 31) * 4;
    int tx = t & 15, ty = t >> 4;

    unsigned long long acc[4][4];
#pragma unroll
    for (int i = 0; i < 4; i++)
#pragma unroll
        for (int j = 0; j < 4; j++) acc[i][j] = 0ull;

    const float* gA = g_feat + (row0 + arow) * KP + ac4;
    const float* gB = g_W1p + bk * HH + col0 + bc4;

    for (int k0 = 0; k0 < KP; k0 += 16) {
        float4 va = *(const float4*)(gA + k0);
        float4 vb0 = *(const float4*)(gB + k0 * HH);
        float4 vb1 = *(const float4*)(gB + (k0 + 8) * HH);
        sA[ac4 + 0][arow] = va.x;
        sA[ac4 + 1][arow] = va.y;
        sA[ac4 + 2][arow] = va.z;
        sA[ac4 + 3][arow] = va.w;
        *(float4*)&sB[bk][bc4] = vb0;
        *(float4*)&sB[bk + 8][bc4] = vb1;
        __syncthreads();
#pragma unroll
        for (int k = 0; k < 16; k++) {
            float4 a = *(const float4*)&sA[k][ty * 4];
            unsigned long long ap0 = pack2(a.x, a.x), ap1 = pack2(a.y, a.y);
            unsigned long long ap2 = pack2(a.z, a.z), ap3 = pack2(a.w, a.w);
            const unsigned long long* bp =
                (const unsigned long long*)&sB[k][tx * 8];
            unsigned long long b0 = bp[0], b1v = bp[1], b2v = bp[2], b3v = bp[3];
            fma2(acc[0][0], ap0, b0);  fma2(acc[0][1], ap0, b1v);
            fma2(acc[0][2], ap0, b2v); fma2(acc[0][3], ap0, b3v);
            fma2(acc[1][0], ap1, b0);  fma2(acc[1][1], ap1, b1v);
            fma2(acc[1][2], ap1, b2v); fma2(acc[1][3], ap1, b3v);
            fma2(acc[2][0], ap2, b0);  fma2(acc[2][1], ap2, b1v);
            fma2(acc[2][2], ap2, b2v); fma2(acc[2][3], ap2, b3v);
            fma2(acc[3][0], ap3, b0);  fma2(acc[3][1], ap3, b1v);
            fma2(acc[3][2], ap3, b2v); fma2(acc[3][3], ap3, b3v);
        }
        __syncthreads();
    }

    float bias[8];
#pragma unroll
    for (int j = 0; j < 8; j++) bias[j] = b1[col0 + tx * 8 + j];
#pragma unroll
    for (int i = 0; i < 4; i++) {
        float o[8];
#pragma unroll
        for (int j = 0; j < 4; j++) {
            float2 v = unpack2(acc[i][j]);
            o[2 * j] = v.x; o[2 * j + 1] = v.y;
        }
#pragma unroll
        for (int j = 0; j < 8; j++) o[j] = fmaxf(o[j] + bias[j], 0.f);
        float* dst = g_h + (size_t)(row0 + ty * 4 + i) * HH + col0 + tx * 8;
        *(float4*)dst = make_float4(o[0], o[1], o[2], o[3]);
        *(float4*)(dst + 4) = make_float4(o[4], o[5], o[6], o[7]);
    }
}

// ---------------------------------------------------------------------------
// GEMM2 + bias + residual + LayerNorm: out = LN(x + h @ W2 + b2)*gamma + beta
// block: 64 rows x 128 cols (full D), BK=16, K=512
// ---------------------------------------------------------------------------
__global__ __launch_bounds__(256) void k_gemm2(
    const float* __restrict__ x, const float* __restrict__ W2,
    const float* __restrict__ b2, const float* __restrict__ gamma,
    const float* __restrict__ beta, float* __restrict__ out, int Nn) {
    __shared__ __align__(16) float sA[16][68];
    __shared__ __align__(16) float sB[16][128];
    int t = threadIdx.x;
    int row0 = blockIdx.x * 64;
    int arow = t >> 2, ac4 = (t & 3) * 4;
    int bk = t >> 5, bc4 = (t & 31) * 4;
    int tx = t & 15, ty = t >> 4;

    unsigned long long acc[4][4];
#pragma unroll
    for (int i = 0; i < 4; i++)
#pragma unroll
        for (int j = 0; j < 4; j++) acc[i][j] = 0ull;

    const float* gA = g_h + (size_t)(row0 + arow) * HH + ac4;
    const float* gB = W2 + bk * DD + bc4;

    for (int k0 = 0; k0 < HH; k0 += 16) {
        float4 va = *(const float4*)(gA + k0);
        float4 vb0 = *(const float4*)(gB + k0 * DD);
        float4 vb1 = *(const float4*)(gB + (k0 + 8) * DD);
        sA[ac4 + 0][arow] = va.x;
        sA[ac4 + 1][arow] = va.y;
        sA[ac4 + 2][arow] = va.z;
        sA[ac4 + 3][arow] = va.w;
        *(float4*)&sB[bk][bc4] = vb0;
        *(float4*)&sB[bk + 8][bc4] = vb1;
        __syncthreads();
#pragma unroll
        for (int k = 0; k < 16; k++) {
            float4 a = *(const float4*)&sA[k][ty * 4];
            unsigned long long ap0 = pack2(a.x, a.x), ap1 = pack2(a.y, a.y);
            unsigned long long ap2 = pack2(a.z, a.z), ap3 = pack2(a.w, a.w);
            const unsigned long long* bp =
                (const unsigned long long*)&sB[k][tx * 8];
            unsigned long long b0 = bp[0], b1v = bp[1], b2v = bp[2], b3v = bp[3];
            fma2(acc[0][0], ap0, b0);  fma2(acc[0][1], ap0, b1v);
            fma2(acc[0][2], ap0, b2v); fma2(acc[0][3], ap0, b3v);
            fma2(acc[1][0], ap1, b0);  fma2(acc[1][1], ap1, b1v);
            fma2(acc[1][2], ap1, b2v); fma2(acc[1][3], ap1, b3v);
            fma2(acc[2][0], ap2, b0);  fma2(acc[2][1], ap2, b1v);
            fma2(acc[2][2], ap2, b2v); fma2(acc[2][3], ap2, b3v);
            fma2(acc[3][0], ap3, b0);  fma2(acc[3][1], ap3, b1v);
            fma2(acc[3][2], ap3, b2v); fma2(acc[3][3], ap3, b3v);
        }
        __syncthreads();
    }

    float bb[8], gg[8], be[8];
#pragma unroll
    for (int j = 0; j < 8; j++) {
        int c = tx * 8 + j;
        bb[j] = b2[c]; gg[j] = gamma[c]; be[j] = beta[c];
    }

#pragma unroll
    for (int i = 0; i < 4; i++) {
        int row = row0 + ty * 4 + i;
        bool valid = (row < Nn);
        float y[8];
        float4 xv0 = make_float4(0.f, 0.f, 0.f, 0.f), xv1 = xv0;
        if (valid) {
            xv0 = *(const float4*)(x + (size_t)row * DD + tx * 8);
            xv1 = *(const float4*)(x + (size_t)row * DD + tx * 8 + 4);
        }
#pragma unroll
        for (int j = 0; j < 4; j++) {
            float2 v = unpack2(acc[i][j]);
            y[2 * j] = v.x; y[2 * j + 1] = v.y;
        }
        y[0] += bb[0] + xv0.x; y[1] += bb[1] + xv0.y;
        y[2] += bb[2] + xv0.z; y[3] += bb[3] + xv0.w;
        y[4] += bb[4] + xv1.x; y[5] += bb[5] + xv1.y;
        y[6] += bb[6] + xv1.z; y[7] += bb[7] + xv1.w;

        float s = 0.f, ss = 0.f;
#pragma unroll
        for (int j = 0; j < 8; j++) { s += y[j]; ss += y[j] * y[j]; }
#pragma unroll
        for (int o = 1; o < 16; o <<= 1) {
            s  += __shfl_xor_sync(0xffffffffu, s, o);
            ss += __shfl_xor_sync(0xffffffffu, ss, o);
        }
        float mu = s * (1.f / 128.f);
        float var = ss * (1.f / 128.f) - mu * mu;
        float rstd = rsqrtf(var + 1e-5f);
        if (valid) {
            float o0[8];
#pragma unroll
            for (int j = 0; j < 8; j++)
                o0[j] = (y[j] - mu) * rstd * gg[j] + be[j];
            float* dst = out + (size_t)row * DD + tx * 8;
            *(float4*)dst = make_float4(o0[0], o0[1], o0[2], o0[3]);
            *(float4*)(dst + 4) = make_float4(o0[4], o0[5], o0[6], o0[7]);
        }
    }
}

// ---------------------------------------------------------------------------
extern "C" void kernel_launch(void* const* d_in, const int* in_sizes, int n_in,
                              void* d_out, int out_size) {
    const float* x       = (const float*)d_in[0];
    const float* W1      = (const float*)d_in[1];
    const float* b1      = (const float*)d_in[2];
    const float* W2      = (const float*)d_in[3];
    const float* b2      = (const float*)d_in[4];
    const float* gamma   = (const float*)d_in[5];
    const float* beta    = (const float*)d_in[6];
    const void*  ei      = d_in[7];
    const float* ed      = (const float*)d_in[8];
    const float* degrees = (const float*)d_in[9];

    int Nn = in_sizes[0] / DD;
    int E  = in_sizes[8];

    k_detect<<<1, 32>>>(ei, E, Nn);
    k_zero<<<(Nn + 255) / 256, 256>>>(Nn);
    k_padW1<<<(KP * HH + 255) / 256, 256>>>(W1);
    k_edge<<<(E + 255) / 256, 256>>>(ei, ed, E, Nn);
    k_feat<<<(Nn + 7) / 8, 256>>>(x, degrees, Nn);

    int rb = (Nn + 63) / 64;
    k_gemm1<<<dim3(rb, 4), 256>>>(b1);
    k_gemm2<<<rb, 256>>>(x, W2, b2, gamma, beta, (float*)d_out, Nn);
}

// round 4
// speedup vs baseline: 2.0879x; 2.0879x over previous
#include <cuda_runtime.h>
#include <cuda_bf16.h>
#include <cstdint>

// ---------------------------------------------------------------------------
// ResidualGNNLayer on sm_103 (no tcgen05 in this toolchain target):
//   edge bucket -> warp-per-node aggregate -> feat bf16 hi/lo (K=272)
//   -> mma.sync bf16x3 GEMM1 (relu, emits h bf16 hi/lo)
//   -> mma.sync bf16x3 GEMM2 + bias + residual + LayerNorm
// ---------------------------------------------------------------------------

#define DD 128
#define HH 512
#define KP 272          // 17 * 16
#define CAP 128
#define NN_MAX 50048    // 391 * 128

static __device__ int   g_is64;
static __device__ int   g_cnt[NN_MAX];
static __device__ float g_dist[NN_MAX];
static __device__ int   g_slots[NN_MAX * CAP];

static __device__ __nv_bfloat16 g_feat_hi[(size_t)NN_MAX * KP];
static __device__ __nv_bfloat16 g_feat_lo[(size_t)NN_MAX * KP];
static __device__ __nv_bfloat16 g_w1t_hi[HH * KP];     // [n][k]
static __device__ __nv_bfloat16 g_w1t_lo[HH * KP];
static __device__ __nv_bfloat16 g_h_hi[(size_t)NN_MAX * HH];
static __device__ __nv_bfloat16 g_h_lo[(size_t)NN_MAX * HH];
static __device__ __nv_bfloat16 g_w2t_hi[DD * HH];     // [n][k]
static __device__ __nv_bfloat16 g_w2t_lo[DD * HH];

// ---------------- PTX helpers ----------------------------------------------
__device__ __forceinline__ uint32_t smem_u32(const void* p) {
    uint32_t a;
    asm("{ .reg .u64 t; cvta.to.shared.u64 t, %1; cvt.u32.u64 %0, t; }"
        : "=r"(a) : "l"(p));
    return a;
}
__device__ __forceinline__ void cp16(uint32_t d, const void* s) {
    asm volatile("cp.async.ca.shared.global [%0], [%1], 16;" :: "r"(d), "l"(s));
}
#define CP_COMMIT() asm volatile("cp.async.commit_group;" ::: "memory")
#define CP_WAIT(n)  asm volatile("cp.async.wait_group %0;" :: "n"(n) : "memory")

__device__ __forceinline__ void ldm_x4(uint32_t addr, uint32_t r[4]) {
    asm volatile("ldmatrix.sync.aligned.m8n8.x4.shared.b16 {%0,%1,%2,%3}, [%4];"
                 : "=r"(r[0]), "=r"(r[1]), "=r"(r[2]), "=r"(r[3]) : "r"(addr));
}
__device__ __forceinline__ void mma16816(float d[4], const uint32_t a[4],
                                         const uint32_t b0, const uint32_t b1) {
    asm volatile(
        "mma.sync.aligned.m16n8k16.row.col.f32.bf16.bf16.f32 "
        "{%0,%1,%2,%3},{%4,%5,%6,%7},{%8,%9},{%0,%1,%2,%3};"
        : "+f"(d[0]), "+f"(d[1]), "+f"(d[2]), "+f"(d[3])
        : "r"(a[0]), "r"(a[1]), "r"(a[2]), "r"(a[3]), "r"(b0), "r"(b1));
}

__device__ __forceinline__ void split2(float a, float b,
                                       __nv_bfloat16* ph, __nv_bfloat16* pl) {
    __nv_bfloat16 ha = __float2bfloat16(a), hb = __float2bfloat16(b);
    __nv_bfloat16 la = __float2bfloat16(a - __bfloat162float(ha));
    __nv_bfloat16 lb = __float2bfloat16(b - __bfloat162float(hb));
    *(__nv_bfloat162*)ph = __halves2bfloat162(ha, hb);
    *(__nv_bfloat162*)pl = __halves2bfloat162(la, lb);
}

// ---------------- small kernels --------------------------------------------
__global__ void k_detect(const void* __restrict__ eraw, int E, int Nn) {
    if (blockIdx.x == 0 && threadIdx.x == 0) {
        const long long* p64 = (const long long*)eraw;
        int ok64 = 1;
        int step = E / 32; if (step < 1) step = 1;
        for (int i = 0; i < 32; i++) {
            long long idx = (long long)i * step;
            if (idx >= E) break;
            long long v = p64[idx];
            if (v < 0 || v >= Nn) { ok64 = 0; break; }
        }
        g_is64 = ok64;
    }
}

__global__ void k_zero(int Nn) {
    int i = blockIdx.x * blockDim.x + threadIdx.x;
    if (i < Nn) { g_cnt[i] = 0; g_dist[i] = 0.f; }
}

__global__ void k_prep_w1(const float* __restrict__ W1) {
    int t = blockIdx.x * blockDim.x + threadIdx.x;
    if (t >= HH * KP) return;
    int n = t / KP, k = t % KP;
    float v = (k < 2 * DD + 2) ? W1[k * HH + n] : 0.f;
    __nv_bfloat16 h = __float2bfloat16(v);
    g_w1t_hi[t] = h;
    g_w1t_lo[t] = __float2bfloat16(v - __bfloat162float(h));
}

__global__ void k_prep_w2(const float* __restrict__ W2) {
    int t = blockIdx.x * blockDim.x + threadIdx.x;
    if (t >= DD * HH) return;
    int n = t / HH, k = t % HH;
    float v = W2[k * DD + n];
    __nv_bfloat16 h = __float2bfloat16(v);
    g_w2t_hi[t] = h;
    g_w2t_lo[t] = __float2bfloat16(v - __bfloat162float(h));
}

__global__ void k_edge(const void* __restrict__ eraw,
                       const float* __restrict__ ed, int E, int Nn) {
    int e = blockIdx.x * blockDim.x + threadIdx.x;
    if (e >= E) return;
    int src, dst;
    if (g_is64) {
        const long long* p = (const long long*)eraw;
        src = (int)p[e]; dst = (int)p[E + e];
    } else {
        const int* p = (const int*)eraw;
        src = p[e]; dst = p[E + e];
    }
    src = min(max(src, 0), Nn - 1);
    dst = min(max(dst, 0), Nn - 1);
    int p = atomicAdd(&g_cnt[src], 1);
    if (p < CAP) g_slots[src * CAP + p] = dst;
    atomicAdd(&g_dist[src], ed[e]);
}

__global__ void k_feat(const float* __restrict__ x,
                       const float* __restrict__ degrees, int Nn) {
    int gw = (blockIdx.x * blockDim.x + threadIdx.x) >> 5;
    int lane = threadIdx.x & 31;
    if (gw >= Nn) return;
    int cnt = g_cnt[gw]; if (cnt > CAP) cnt = CAP;
    const int* slots = g_slots + gw * CAP;
    float4 acc = make_float4(0.f, 0.f, 0.f, 0.f);
    int dnext = (cnt > 0) ? slots[0] : 0;
    for (int j = 0; j < cnt; j++) {
        int dcur = dnext;
        if (j + 1 < cnt) dnext = slots[j + 1];
        float4 v = *(const float4*)(x + (size_t)dcur * DD + lane * 4);
        acc.x += v.x; acc.y += v.y; acc.z += v.z; acc.w += v.w;
    }
    float degRaw = degrees[gw];
    float inv = 1.f / fmaxf(degRaw, 1.f);
    __nv_bfloat16* fh = g_feat_hi + (size_t)gw * KP;
    __nv_bfloat16* fl = g_feat_lo + (size_t)gw * KP;
    float4 xv = *(const float4*)(x + (size_t)gw * DD + lane * 4);
    split2(xv.x, xv.y, fh + lane * 4, fl + lane * 4);
    split2(xv.z, xv.w, fh + lane * 4 + 2, fl + lane * 4 + 2);
    split2(acc.x * inv, acc.y * inv, fh + DD + lane * 4, fl + DD + lane * 4);
    split2(acc.z * inv, acc.w * inv, fh + DD + lane * 4 + 2, fl + DD + lane * 4 + 2);
    if (lane < 8) {
        float c0 = 0.f, c1 = 0.f;
        if (lane == 0) { c0 = degRaw; c1 = g_dist[gw] * inv; }
        split2(c0, c1, fh + 2 * DD + lane * 2, fl + 2 * DD + lane * 2);
    }
}

// ---------------------------------------------------------------------------
// GEMM cores: block 128x128, 8 warps (2x4) of 64x32, BK=16, bf16x3 split.
// smem stage (16KB): Ah @0, Al @4096, Bh @8192, Bl @12288; 2 stages.
// ---------------------------------------------------------------------------
struct Frags {
    uint32_t Ah[4][4], Al[4][4];
    uint32_t Bh[4][2], Bl[4][2];
};

__device__ __forceinline__ void load_frags(uint32_t sb, int wm, int wn, int lane,
                                           Frags& f) {
#pragma unroll
    for (int mf = 0; mf < 4; mf++) {
        uint32_t addr = sb + ((wm * 64 + mf * 16 + (lane & 15)) * 16 +
                              (lane >> 4) * 8) * 2;
        ldm_x4(addr, f.Ah[mf]);
        ldm_x4(addr + 4096, f.Al[mf]);
    }
#pragma unroll
    for (int p = 0; p < 2; p++) {
        uint32_t addr = sb + 8192 + ((wn * 32 + p * 16 + (lane & 15)) * 16 +
                                     (lane >> 4) * 8) * 2;
        uint32_t r[4];
        ldm_x4(addr, r);
        f.Bh[p * 2 + 0][0] = r[0]; f.Bh[p * 2 + 0][1] = r[2];
        f.Bh[p * 2 + 1][0] = r[1]; f.Bh[p * 2 + 1][1] = r[3];
        ldm_x4(addr + 4096, r);
        f.Bl[p * 2 + 0][0] = r[0]; f.Bl[p * 2 + 0][1] = r[2];
        f.Bl[p * 2 + 1][0] = r[1]; f.Bl[p * 2 + 1][1] = r[3];
    }
}

__device__ __forceinline__ void mma_all(float acc[4][4][4], const Frags& f) {
#pragma unroll
    for (int mf = 0; mf < 4; mf++)
#pragma unroll
        for (int nf = 0; nf < 4; nf++) {
            mma16816(acc[mf][nf], f.Ah[mf], f.Bh[nf][0], f.Bh[nf][1]);
            mma16816(acc[mf][nf], f.Al[mf], f.Bh[nf][0], f.Bh[nf][1]);
            mma16816(acc[mf][nf], f.Ah[mf], f.Bl[nf][0], f.Bl[nf][1]);
        }
}

// GEMM1: h = relu(feat @ W1 + b1), K=272 (17 steps)
__global__ __launch_bounds__(256) void k_gemm1(const float* __restrict__ b1) {
    extern __shared__ __align__(128) char sm[];
    int t = threadIdx.x, lane = t & 31, wid = t >> 5;
    int row0 = blockIdx.x * 128, col0 = blockIdx.y * 128;
    int wm = wid >> 2, wn = wid & 3;

    float acc[4][4][4];
#pragma unroll
    for (int a = 0; a < 4; a++)
#pragma unroll
        for (int b = 0; b < 4; b++)
#pragma unroll
            for (int c = 0; c < 4; c++) acc[a][b][c] = 0.f;

    int lr = t >> 1, lkB = (t & 1) * 16;
    const char* sAh = (const char*)(g_feat_hi + (size_t)(row0 + lr) * KP) + lkB;
    const char* sAl = (const char*)(g_feat_lo + (size_t)(row0 + lr) * KP) + lkB;
    const char* sBh = (const char*)(g_w1t_hi + (size_t)(col0 + lr) * KP) + lkB;
    const char* sBl = (const char*)(g_w1t_lo + (size_t)(col0 + lr) * KP) + lkB;
    uint32_t dsh = smem_u32(sm) + lr * 32 + lkB;

    const int NS = KP / 16;  // 17
#pragma unroll 1
    for (int s = 0; s < 2; s++) {
        uint32_t d = dsh + (s & 1) * 16384;
        cp16(d, sAh + s * 32);
        cp16(d + 4096, sAl + s * 32);
        cp16(d + 8192, sBh + s * 32);
        cp16(d + 12288, sBl + s * 32);
        CP_COMMIT();
    }
#pragma unroll 1
    for (int s = 0; s < NS; s++) {
        if (s + 1 < NS) { CP_WAIT(1); } else { CP_WAIT(0); }
        __syncthreads();
        uint32_t sb = smem_u32(sm) + (s & 1) * 16384;
        Frags f;
        load_frags(sb, wm, wn, lane, f);
        mma_all(acc, f);
        __syncthreads();
        if (s + 2 < NS) {
            uint32_t d = dsh + ((s + 2) & 1) * 16384;
            cp16(d, sAh + (s + 2) * 32);
            cp16(d + 4096, sAl + (s + 2) * 32);
            cp16(d + 8192, sBh + (s + 2) * 32);
            cp16(d + 12288, sBl + (s + 2) * 32);
            CP_COMMIT();
        }
    }

    // epilogue: relu(+bias), split hi/lo, store h
#pragma unroll
    for (int mf = 0; mf < 4; mf++)
#pragma unroll
        for (int nf = 0; nf < 4; nf++) {
            int rr = row0 + wm * 64 + mf * 16 + (lane >> 2);
            int cc = col0 + wn * 32 + nf * 8 + (lane & 3) * 2;
            float bi0 = __ldg(b1 + cc), bi1 = __ldg(b1 + cc + 1);
            float v0 = fmaxf(acc[mf][nf][0] + bi0, 0.f);
            float v1 = fmaxf(acc[mf][nf][1] + bi1, 0.f);
            float v2 = fmaxf(acc[mf][nf][2] + bi0, 0.f);
            float v3 = fmaxf(acc[mf][nf][3] + bi1, 0.f);
            split2(v0, v1, g_h_hi + (size_t)rr * HH + cc,
                           g_h_lo + (size_t)rr * HH + cc);
            split2(v2, v3, g_h_hi + (size_t)(rr + 8) * HH + cc,
                           g_h_lo + (size_t)(rr + 8) * HH + cc);
        }
}

// GEMM2 + bias + residual + LN, K=512 (32 steps), N=128
#define YB_OFF 32768
__global__ __launch_bounds__(256) void k_gemm2(
    const float* __restrict__ x, const float* __restrict__ b2,
    const float* __restrict__ gamma, const float* __restrict__ beta,
    float* __restrict__ out, int Nn) {
    extern __shared__ __align__(128) char sm[];
    int t = threadIdx.x, lane = t & 31, wid = t >> 5;
    int row0 = blockIdx.x * 128;
    int wm = wid >> 2, wn = wid & 3;

    float acc[4][4][4];
#pragma unroll
    for (int a = 0; a < 4; a++)
#pragma unroll
        for (int b = 0; b < 4; b++)
#pragma unroll
            for (int c = 0; c < 4; c++) acc[a][b][c] = 0.f;

    int lr = t >> 1, lkB = (t & 1) * 16;
    const char* sAh = (const char*)(g_h_hi + (size_t)(row0 + lr) * HH) + lkB;
    const char* sAl = (const char*)(g_h_lo + (size_t)(row0 + lr) * HH) + lkB;
    const char* sBh = (const char*)(g_w2t_hi + (size_t)lr * HH) + lkB;
    const char* sBl = (const char*)(g_w2t_lo + (size_t)lr * HH) + lkB;
    uint32_t dsh = smem_u32(sm) + lr * 32 + lkB;

    const int NS = HH / 16;  // 32
#pragma unroll 1
    for (int s = 0; s < 2; s++) {
        uint32_t d = dsh + (s & 1) * 16384;
        cp16(d, sAh + s * 32);
        cp16(d + 4096, sAl + s * 32);
        cp16(d + 8192, sBh + s * 32);
        cp16(d + 12288, sBl + s * 32);
        CP_COMMIT();
    }
#pragma unroll 1
    for (int s = 0; s < NS; s++) {
        if (s + 1 < NS) { CP_WAIT(1); } else { CP_WAIT(0); }
        __syncthreads();
        uint32_t sb = smem_u32(sm) + (s & 1) * 16384;
        Frags f;
        load_frags(sb, wm, wn, lane, f);
        mma_all(acc, f);
        __syncthreads();
        if (s + 2 < NS) {
            uint32_t d = dsh + ((s + 2) & 1) * 16384;
            cp16(d, sAh + (s + 2) * 32);
            cp16(d + 4096, sAl + (s + 2) * 32);
            cp16(d + 8192, sBh + (s + 2) * 32);
            cp16(d + 12288, sBl + (s + 2) * 32);
            CP_COMMIT();
        }
    }

    // epilogue: y = d + b2 + x -> smem; per-row LN; store
    float* yb = (float*)(sm + YB_OFF);           // [128][129]
    float* mus = (float*)(sm + YB_OFF + 66048);
    float* rss = (float*)(sm + YB_OFF + 66048 + 512);
#pragma unroll
    for (int mf = 0; mf < 4; mf++)
#pragma unroll
        for (int nf = 0; nf < 4; nf++) {
            int rl = wm * 64 + mf * 16 + (lane >> 2);
            int cc = wn * 32 + nf * 8 + (lane & 3) * 2;
            float bi0 = __ldg(b2 + cc), bi1 = __ldg(b2 + cc + 1);
            int g0 = row0 + rl, g1 = g0 + 8;
            float x00 = 0.f, x01 = 0.f, x10 = 0.f, x11 = 0.f;
            if (g0 < Nn) {
                float2 v = *(const float2*)(x + (size_t)g0 * DD + cc);
                x00 = v.x; x01 = v.y;
            }
            if (g1 < Nn) {
                float2 v = *(const float2*)(x + (size_t)g1 * DD + cc);
                x10 = v.x; x11 = v.y;
            }
            yb[rl * 129 + cc]       = acc[mf][nf][0] + bi0 + x00;
            yb[rl * 129 + cc + 1]   = acc[mf][nf][1] + bi1 + x01;
            yb[(rl + 8) * 129 + cc]     = acc[mf][nf][2] + bi0 + x10;
            yb[(rl + 8) * 129 + cc + 1] = acc[mf][nf][3] + bi1 + x11;
        }
    __syncthreads();
    if (t < 128) {
        const float* r = yb + t * 129;
        float s0 = 0.f, s1 = 0.f;
#pragma unroll
        for (int c = 0; c < 128; c++) { float v = r[c]; s0 += v; s1 += v * v; }
        float mu = s0 * (1.f / 128.f);
        float var = s1 * (1.f / 128.f) - mu * mu;
        mus[t] = mu;
        rss[t] = rsqrtf(var + 1e-5f);
    }
    __syncthreads();
#pragma unroll
    for (int i = 0; i < 64; i++) {
        int w = t + i * 256;
        int row = w >> 7, col = w & 127;
        int grow = row0 + row;
        if (grow < Nn) {
            float v = yb[row * 129 + col];
            out[(size_t)grow * DD + col] =
                (v - mus[row]) * rss[row] * __ldg(gamma + col) + __ldg(beta + col);
        }
    }
}

// ---------------------------------------------------------------------------
extern "C" void kernel_launch(void* const* d_in, const int* in_sizes, int n_in,
                              void* d_out, int out_size) {
    const float* x       = (const float*)d_in[0];
    const float* W1      = (const float*)d_in[1];
    const float* b1      = (const float*)d_in[2];
    const float* W2      = (const float*)d_in[3];
    const float* b2      = (const float*)d_in[4];
    const float* gamma   = (const float*)d_in[5];
    const float* beta    = (const float*)d_in[6];
    const void*  ei      = d_in[7];
    const float* ed      = (const float*)d_in[8];
    const float* degrees = (const float*)d_in[9];

    int Nn = in_sizes[0] / DD;
    int E  = in_sizes[8];

    static int s_attr_done = 0;
    if (!s_attr_done) {
        cudaFuncSetAttribute(k_gemm2, cudaFuncAttributeMaxDynamicSharedMemorySize,
                             YB_OFF + 66048 + 1024);
        cudaFuncSetAttribute(k_gemm1, cudaFuncAttributeMaxDynamicSharedMemorySize,
                             32768);
        s_attr_done = 1;
    }

    k_detect<<<1, 32>>>(ei, E, Nn);
    k_zero<<<(Nn + 255) / 256, 256>>>(Nn);
    k_prep_w1<<<(HH * KP + 255) / 256, 256>>>(W1);
    k_prep_w2<<<(DD * HH + 255) / 256, 256>>>(W2);
    k_edge<<<(E + 255) / 256, 256>>>(ei, ed, E, Nn);
    k_feat<<<(Nn + 7) / 8, 256>>>(x, degrees, Nn);

    int mt = (Nn + 127) / 128;  // 391
    k_gemm1<<<dim3(mt, 4), 256, 32768>>>(b1);
    k_gemm2<<<mt, 256, YB_OFF + 66048 + 1024>>>(x, b2, gamma, beta,
                                                (float*)d_out, Nn);
}

// round 5
// speedup vs baseline: 2.5937x; 1.2423x over previous
#include <cuda_runtime.h>
#include <cuda_bf16.h>
#include <cstdint>

// ---------------------------------------------------------------------------
// ResidualGNNLayer (sm_103, mma.sync bf16x3 path):
//   k_prep  : detect idx dtype + zero counters + split/transpose W1, W2
//   k_edge  : bucket edges by src
//   k_feat  : warp-per-node gather-mean -> feat bf16 hi/lo (K=256: x|agg)
//   k_fused : per 128-row tile: GEMM1(K=256)+bias+rank2(deg,md)+relu -> h in
//             smem (bf16 hi/lo) -> GEMM2(K=512 via 4 chunks) + residual + LN
// ---------------------------------------------------------------------------

#define DD 128
#define HH 512
#define KP 256
#define CAP 128
#define NN_MAX 50048    // 391 * 128

static __device__ int   g_is64;
static __device__ int   g_cnt[NN_MAX];
static __device__ float g_dist[NN_MAX];
static __device__ int   g_slots[NN_MAX * CAP];

static __device__ __nv_bfloat16 g_feat_hi[(size_t)NN_MAX * KP];
static __device__ __nv_bfloat16 g_feat_lo[(size_t)NN_MAX * KP];
static __device__ __nv_bfloat16 g_w1t_hi[HH * KP];     // [n=512][k=256]
static __device__ __nv_bfloat16 g_w1t_lo[HH * KP];
static __device__ __nv_bfloat16 g_w2t_hi[DD * HH];     // [n=128][k=512]
static __device__ __nv_bfloat16 g_w2t_lo[DD * HH];

// ---------------- PTX helpers ----------------------------------------------
__device__ __forceinline__ uint32_t smem_u32(const void* p) {
    uint32_t a;
    asm("{ .reg .u64 t; cvta.to.shared.u64 t, %1; cvt.u32.u64 %0, t; }"
        : "=r"(a) : "l"(p));
    return a;
}
__device__ __forceinline__ void cp16(uint32_t d, const void* s) {
    asm volatile("cp.async.ca.shared.global [%0], [%1], 16;" :: "r"(d), "l"(s));
}
#define CP_COMMIT() asm volatile("cp.async.commit_group;" ::: "memory")
#define CP_WAIT(n)  asm volatile("cp.async.wait_group %0;" :: "n"(n) : "memory")

__device__ __forceinline__ void ldm_x4(uint32_t addr, uint32_t r[4]) {
    asm volatile("ldmatrix.sync.aligned.m8n8.x4.shared.b16 {%0,%1,%2,%3}, [%4];"
                 : "=r"(r[0]), "=r"(r[1]), "=r"(r[2]), "=r"(r[3]) : "r"(addr));
}
__device__ __forceinline__ void mma16816(float d[4], const uint32_t a[4],
                                         const uint32_t b0, const uint32_t b1) {
    asm volatile(
        "mma.sync.aligned.m16n8k16.row.col.f32.bf16.bf16.f32 "
        "{%0,%1,%2,%3},{%4,%5,%6,%7},{%8,%9},{%0,%1,%2,%3};"
        : "+f"(d[0]), "+f"(d[1]), "+f"(d[2]), "+f"(d[3])
        : "r"(a[0]), "r"(a[1]), "r"(a[2]), "r"(a[3]), "r"(b0), "r"(b1));
}
__device__ __forceinline__ void split2(float a, float b,
                                       __nv_bfloat16* ph, __nv_bfloat16* pl) {
    __nv_bfloat16 ha = __float2bfloat16(a), hb = __float2bfloat16(b);
    __nv_bfloat16 la = __float2bfloat16(a - __bfloat162float(ha));
    __nv_bfloat16 lb = __float2bfloat16(b - __bfloat162float(hb));
    *(__nv_bfloat162*)ph = __halves2bfloat162(ha, hb);
    *(__nv_bfloat162*)pl = __halves2bfloat162(la, lb);
}
// swizzled offset inside a [128 rows][64B] tile: conflict-free ldmatrix
__device__ __forceinline__ uint32_t swz(int r, int c) {
    return (uint32_t)(r * 64 + (((((c >> 4) ^ (r >> 1)) & 3) << 4) | (c & 15)));
}

// ---------------- prep: detect + zero + weight split ------------------------
__global__ void k_prep(const float* __restrict__ W1, const float* __restrict__ W2,
                       const void* __restrict__ eraw, int E, int Nn) {
    int b = blockIdx.x, t = threadIdx.x;
    if (b == 0) {
        if (t == 0) {
            const long long* p64 = (const long long*)eraw;
            int ok64 = 1;
            int step = E / 32; if (step < 1) step = 1;
            for (int i = 0; i < 32; i++) {
                long long idx = (long long)i * step;
                if (idx >= E) break;
                long long v = p64[idx];
                if (v < 0 || v >= Nn) { ok64 = 0; break; }
            }
            g_is64 = ok64;
        }
        return;
    }
    int ZB = (Nn + 255) / 256;
    if (b - 1 < ZB) {
        int i = (b - 1) * 256 + t;
        if (i < Nn) { g_cnt[i] = 0; g_dist[i] = 0.f; }
        return;
    }
    int b2 = b - 1 - ZB;
    if (b2 < (HH * KP) / 256) {           // W1 -> [n][k] hi/lo (k<256 only)
        int idx = b2 * 256 + t;
        int n = idx >> 8, k = idx & 255;
        float v = W1[k * HH + n];
        __nv_bfloat16 h = __float2bfloat16(v);
        g_w1t_hi[idx] = h;
        g_w1t_lo[idx] = __float2bfloat16(v - __bfloat162float(h));
        return;
    }
    int b3 = b2 - (HH * KP) / 256;        // W2 -> [n][k] hi/lo
    int idx = b3 * 256 + t;
    int n = idx >> 9, k = idx & 511;
    float v = W2[k * DD + n];
    __nv_bfloat16 h = __float2bfloat16(v);
    g_w2t_hi[idx] = h;
    g_w2t_lo[idx] = __float2bfloat16(v - __bfloat162float(h));
}

__global__ void k_edge(const void* __restrict__ eraw,
                       const float* __restrict__ ed, int E, int Nn) {
    int e = blockIdx.x * blockDim.x + threadIdx.x;
    if (e >= E) return;
    int src, dst;
    if (g_is64) {
        const long long* p = (const long long*)eraw;
        src = (int)p[e]; dst = (int)p[E + e];
    } else {
        const int* p = (const int*)eraw;
        src = p[e]; dst = p[E + e];
    }
    src = min(max(src, 0), Nn - 1);
    dst = min(max(dst, 0), Nn - 1);
    int p = atomicAdd(&g_cnt[src], 1);
    if (p < CAP) g_slots[src * CAP + p] = dst;
    atomicAdd(&g_dist[src], ed[e]);
}

__global__ void k_feat(const float* __restrict__ x,
                       const float* __restrict__ degrees, int Nn) {
    int gw = (blockIdx.x * blockDim.x + threadIdx.x) >> 5;
    int lane = threadIdx.x & 31;
    if (gw >= Nn) return;
    int cnt = g_cnt[gw]; if (cnt > CAP) cnt = CAP;
    const int* slots = g_slots + gw * CAP;
    float4 acc = make_float4(0.f, 0.f, 0.f, 0.f);
    int dnext = (cnt > 0) ? slots[0] : 0;
    for (int j = 0; j < cnt; j++) {
        int dcur = dnext;
        if (j + 1 < cnt) dnext = slots[j + 1];
        float4 v = *(const float4*)(x + (size_t)dcur * DD + lane * 4);
        acc.x += v.x; acc.y += v.y; acc.z += v.z; acc.w += v.w;
    }
    float inv = 1.f / fmaxf(degrees[gw], 1.f);
    __nv_bfloat16* fh = g_feat_hi + (size_t)gw * KP;
    __nv_bfloat16* fl = g_feat_lo + (size_t)gw * KP;
    float4 xv = *(const float4*)(x + (size_t)gw * DD + lane * 4);
    split2(xv.x, xv.y, fh + lane * 4, fl + lane * 4);
    split2(xv.z, xv.w, fh + lane * 4 + 2, fl + lane * 4 + 2);
    split2(acc.x * inv, acc.y * inv, fh + DD + lane * 4, fl + DD + lane * 4);
    split2(acc.z * inv, acc.w * inv, fh + DD + lane * 4 + 2, fl + DD + lane * 4 + 2);
}

// ---------------------------------------------------------------------------
// Fused GEMM1 -> GEMM2 -> LN. Block = 128 rows, 256 threads (2x4 warps).
// smem: stages[2] 32KB @0 (Ah,Al,Bh,Bl 8KB each); hbuf hi @65536, lo @100352
//       ([128][136] bf16); degv @135168, mdv @135680; LN reuses @0.
// ---------------------------------------------------------------------------
#define STG(s)   ((s) * 32768)
#define HB_HI    65536
#define HB_LO    100352
#define OF_DEG   135168
#define OF_MD    135680
#define OF_MUS   67584
#define OF_RSS   68096
#define SMEM_REQ 136192

struct Frags {
    uint32_t Ah[4][4], Al[4][4];
    uint32_t Bh[4][2], Bl[4][2];
};
__device__ __forceinline__ void load_B(uint32_t sbB, int wn, int lane, int ks,
                                       Frags& f) {
#pragma unroll
    for (int p = 0; p < 2; p++) {
        uint32_t addr = sbB + swz(wn * 32 + p * 16 + (lane & 15),
                                  ks * 32 + (lane >> 4) * 16);
        uint32_t r[4];
        ldm_x4(addr, r);
        f.Bh[p * 2 + 0][0] = r[0]; f.Bh[p * 2 + 0][1] = r[2];
        f.Bh[p * 2 + 1][0] = r[1]; f.Bh[p * 2 + 1][1] = r[3];
        ldm_x4(addr + 8192, r);
        f.Bl[p * 2 + 0][0] = r[0]; f.Bl[p * 2 + 0][1] = r[2];
        f.Bl[p * 2 + 1][0] = r[1]; f.Bl[p * 2 + 1][1] = r[3];
    }
}
__device__ __forceinline__ void mma_all(float acc[4][4][4], const Frags& f) {
#pragma unroll
    for (int mf = 0; mf < 4; mf++)
#pragma unroll
        for (int nf = 0; nf < 4; nf++) {
            mma16816(acc[mf][nf], f.Ah[mf], f.Bh[nf][0], f.Bh[nf][1]);
            mma16816(acc[mf][nf], f.Al[mf], f.Bh[nf][0], f.Bh[nf][1]);
            mma16816(acc[mf][nf], f.Ah[mf], f.Bl[nf][0], f.Bl[nf][1]);
        }
}

__global__ __launch_bounds__(256) void k_fused(
    const float* __restrict__ x, const float* __restrict__ W1,
    const float* __restrict__ b1, const float* __restrict__ b2,
    const float* __restrict__ gamma, const float* __restrict__ beta,
    const float* __restrict__ degrees, float* __restrict__ out, int Nn) {
    extern __shared__ __align__(128) char sm[];
    uint32_t base = smem_u32(sm);
    int t = threadIdx.x, lane = t & 31, wid = t >> 5;
    int wm = wid >> 2, wn = wid & 3;
    int row0 = blockIdx.x * 128;

    float* degv = (float*)(sm + OF_DEG);
    float* mdv  = (float*)(sm + OF_MD);
    if (t < 128) {
        int gr = row0 + t;
        float dr = (gr < Nn) ? degrees[gr] : 0.f;
        float ds = (gr < Nn) ? g_dist[gr] : 0.f;
        degv[t] = dr;
        mdv[t]  = ds / fmaxf(dr, 1.f);
    }

    float acc2[4][4][4];
#pragma unroll
    for (int a = 0; a < 4; a++)
#pragma unroll
        for (int b = 0; b < 4; b++)
#pragma unroll
            for (int c = 0; c < 4; c++) acc2[a][b][c] = 0.f;

    int lr = t >> 1, hb = (t & 1) * 32;   // loader row / byte-half
    const char* pAh = (const char*)(g_feat_hi + (size_t)(row0 + lr) * KP) + hb;
    const char* pAl = (const char*)(g_feat_lo + (size_t)(row0 + lr) * KP) + hb;
    uint32_t dA0 = base + swz(lr, hb), dA1 = base + swz(lr, hb + 16);

#pragma unroll 1
    for (int nc = 0; nc < 4; nc++) {
        float acc1[4][4][4];
#pragma unroll
        for (int a = 0; a < 4; a++)
#pragma unroll
            for (int b = 0; b < 4; b++)
#pragma unroll
                for (int c = 0; c < 4; c++) acc1[a][b][c] = 0.f;

        const char* pBh = (const char*)(g_w1t_hi + (size_t)(nc * 128 + lr) * KP) + hb;
        const char* pBl = (const char*)(g_w1t_lo + (size_t)(nc * 128 + lr) * KP) + hb;

        // ---- GEMM1: K=256, 8 steps of 32 ----
#pragma unroll 1
        for (int s = 0; s < 2; s++) {
            uint32_t d0 = dA0 + STG(s), d1 = dA1 + STG(s);
            cp16(d0, pAh + s * 64);          cp16(d1, pAh + s * 64 + 16);
            cp16(d0 + 8192, pAl + s * 64);   cp16(d1 + 8192, pAl + s * 64 + 16);
            cp16(d0 + 16384, pBh + s * 64);  cp16(d1 + 16384, pBh + s * 64 + 16);
            cp16(d0 + 24576, pBl + s * 64);  cp16(d1 + 24576, pBl + s * 64 + 16);
            CP_COMMIT();
        }
#pragma unroll 1
        for (int s = 0; s < 8; s++) {
            if (s < 7) { CP_WAIT(1); } else { CP_WAIT(0); }
            __syncthreads();
            uint32_t sb = base + STG(s & 1);
#pragma unroll
            for (int ks = 0; ks < 2; ks++) {
                Frags f;
#pragma unroll
                for (int mf = 0; mf < 4; mf++) {
                    uint32_t a = sb + swz(wm * 64 + mf * 16 + (lane & 15),
                                          ks * 32 + (lane >> 4) * 16);
                    ldm_x4(a, f.Ah[mf]);
                    ldm_x4(a + 8192, f.Al[mf]);
                }
                load_B(sb + 16384, wn, lane, ks, f);
                mma_all(acc1, f);
            }
            __syncthreads();
            if (s + 2 < 8) {
                uint32_t d0 = dA0 + STG(s & 1), d1 = dA1 + STG(s & 1);
                cp16(d0, pAh + (s + 2) * 64);         cp16(d1, pAh + (s + 2) * 64 + 16);
                cp16(d0 + 8192, pAl + (s + 2) * 64);  cp16(d1 + 8192, pAl + (s + 2) * 64 + 16);
                cp16(d0 + 16384, pBh + (s + 2) * 64); cp16(d1 + 16384, pBh + (s + 2) * 64 + 16);
                cp16(d0 + 24576, pBl + (s + 2) * 64); cp16(d1 + 24576, pBl + (s + 2) * 64 + 16);
                CP_COMMIT();
            }
        }

        // ---- chunk epilogue: bias + rank-2(deg,md) + relu -> hbuf hi/lo ----
#pragma unroll
        for (int mf = 0; mf < 4; mf++) {
            int rl = wm * 64 + mf * 16 + (lane >> 2);
            float d0 = degv[rl], m0 = mdv[rl];
            float d1 = degv[rl + 8], m1 = mdv[rl + 8];
#pragma unroll
            for (int nf = 0; nf < 4; nf++) {
                int cl = wn * 32 + nf * 8 + (lane & 3) * 2;
                int cg = nc * 128 + cl;
                float b10 = __ldg(b1 + cg), b11 = __ldg(b1 + cg + 1);
                float wd0 = __ldg(W1 + 256 * HH + cg), wd1 = __ldg(W1 + 256 * HH + cg + 1);
                float wm0 = __ldg(W1 + 257 * HH + cg), wm1 = __ldg(W1 + 257 * HH + cg + 1);
                float v00 = fmaxf(acc1[mf][nf][0] + b10 + d0 * wd0 + m0 * wm0, 0.f);
                float v01 = fmaxf(acc1[mf][nf][1] + b11 + d0 * wd1 + m0 * wm1, 0.f);
                float v10 = fmaxf(acc1[mf][nf][2] + b10 + d1 * wd0 + m1 * wm0, 0.f);
                float v11 = fmaxf(acc1[mf][nf][3] + b11 + d1 * wd1 + m1 * wm1, 0.f);
                split2(v00, v01,
                       (__nv_bfloat16*)(sm + HB_HI + (rl * 136 + cl) * 2),
                       (__nv_bfloat16*)(sm + HB_LO + (rl * 136 + cl) * 2));
                split2(v10, v11,
                       (__nv_bfloat16*)(sm + HB_HI + ((rl + 8) * 136 + cl) * 2),
                       (__nv_bfloat16*)(sm + HB_LO + ((rl + 8) * 136 + cl) * 2));
            }
        }
        // prefetch W2 k-slices for this chunk (stages free after GEMM1)
        const char* pWh = (const char*)(g_w2t_hi + (size_t)lr * HH + nc * 128) + hb;
        const char* pWl = (const char*)(g_w2t_lo + (size_t)lr * HH + nc * 128) + hb;
#pragma unroll 1
        for (int s = 0; s < 2; s++) {
            uint32_t d0 = dA0 + STG(s), d1 = dA1 + STG(s);
            cp16(d0 + 16384, pWh + s * 64);  cp16(d1 + 16384, pWh + s * 64 + 16);
            cp16(d0 + 24576, pWl + s * 64);  cp16(d1 + 24576, pWl + s * 64 + 16);
            CP_COMMIT();
        }
        __syncthreads();   // hbuf visible to all warps

        // ---- GEMM2 partial: 4 steps of 32 over this 128-k chunk ----
#pragma unroll 1
        for (int s = 0; s < 4; s++) {
            if (s < 3) { CP_WAIT(1); } else { CP_WAIT(0); }
            __syncthreads();
            uint32_t sb = base + STG(s & 1);
#pragma unroll
            for (int ks = 0; ks < 2; ks++) {
                Frags f;
#pragma unroll
                for (int mf = 0; mf < 4; mf++) {
                    uint32_t a = base + HB_HI +
                        (uint32_t)((wm * 64 + mf * 16 + (lane & 15)) * 272 +
                                   s * 64 + ks * 32 + (lane >> 4) * 16);
                    ldm_x4(a, f.Ah[mf]);
                    ldm_x4(a + (HB_LO - HB_HI), f.Al[mf]);
                }
                load_B(sb + 16384, wn, lane, ks, f);
                mma_all(acc2, f);
            }
            __syncthreads();
            if (s + 2 < 4) {
                uint32_t d0 = dA0 + STG(s & 1), d1 = dA1 + STG(s & 1);
                cp16(d0 + 16384, pWh + (s + 2) * 64);  cp16(d1 + 16384, pWh + (s + 2) * 64 + 16);
                cp16(d0 + 24576, pWl + (s + 2) * 64);  cp16(d1 + 24576, pWl + (s + 2) * 64 + 16);
                CP_COMMIT();
            }
        }
    }

    // ---- final epilogue: + b2 + x, LayerNorm, store ----
    float* yb  = (float*)sm;                 // [128][129]
    float* mus = (float*)(sm + OF_MUS);
    float* rss = (float*)(sm + OF_RSS);
#pragma unroll
    for (int mf = 0; mf < 4; mf++)
#pragma unroll
        for (int nf = 0; nf < 4; nf++) {
            int rl = wm * 64 + mf * 16 + (lane >> 2);
            int cc = wn * 32 + nf * 8 + (lane & 3) * 2;
            float bi0 = __ldg(b2 + cc), bi1 = __ldg(b2 + cc + 1);
            int g0 = row0 + rl, g1 = g0 + 8;
            float x00 = 0.f, x01 = 0.f, x10 = 0.f, x11 = 0.f;
            if (g0 < Nn) {
                float2 v = *(const float2*)(x + (size_t)g0 * DD + cc);
                x00 = v.x; x01 = v.y;
            }
            if (g1 < Nn) {
                float2 v = *(const float2*)(x + (size_t)g1 * DD + cc);
                x10 = v.x; x11 = v.y;
            }
            yb[rl * 129 + cc]           = acc2[mf][nf][0] + bi0 + x00;
            yb[rl * 129 + cc + 1]       = acc2[mf][nf][1] + bi1 + x01;
            yb[(rl + 8) * 129 + cc]     = acc2[mf][nf][2] + bi0 + x10;
            yb[(rl + 8) * 129 + cc + 1] = acc2[mf][nf][3] + bi1 + x11;
        }
    __syncthreads();
    if (t < 128) {
        const float* r = yb + t * 129;
        float s0 = 0.f, s1 = 0.f;
#pragma unroll
        for (int c = 0; c < 128; c++) { float v = r[c]; s0 += v; s1 += v * v; }
        float mu = s0 * (1.f / 128.f);
        float var = s1 * (1.f / 128.f) - mu * mu;
        mus[t] = mu;
        rss[t] = rsqrtf(var + 1e-5f);
    }
    __syncthreads();
#pragma unroll
    for (int i = 0; i < 64; i++) {
        int w = t + i * 256;
        int row = w >> 7, col = w & 127;
        int grow = row0 + row;
        if (grow < Nn) {
            float v = yb[row * 129 + col];
            out[(size_t)grow * DD + col] =
                (v - mus[row]) * rss[row] * __ldg(gamma + col) + __ldg(beta + col);
        }
    }
}

// ---------------------------------------------------------------------------
extern "C" void kernel_launch(void* const* d_in, const int* in_sizes, int n_in,
                              void* d_out, int out_size) {
    const float* x       = (const float*)d_in[0];
    const float* W1      = (const float*)d_in[1];
    const float* b1      = (const float*)d_in[2];
    const float* W2      = (const float*)d_in[3];
    const float* b2      = (const float*)d_in[4];
    const float* gamma   = (const float*)d_in[5];
    const float* beta    = (const float*)d_in[6];
    const void*  ei      = d_in[7];
    const float* ed      = (const float*)d_in[8];
    const float* degrees = (const float*)d_in[9];

    int Nn = in_sizes[0] / DD;
    int E  = in_sizes[8];

    cudaFuncSetAttribute(k_fused, cudaFuncAttributeMaxDynamicSharedMemorySize,
                         SMEM_REQ);

    int ZB = (Nn + 255) / 256;
    int prep_blocks = 1 + ZB + (HH * KP) / 256 + (DD * HH) / 256;
    k_prep<<<prep_blocks, 256>>>(W1, W2, ei, E, Nn);
    k_edge<<<(E + 255) / 256, 256>>>(ei, ed, E, Nn);
    k_feat<<<(Nn + 7) / 8, 256>>>(x, degrees, Nn);

    int mt = (Nn + 127) / 128;  // 391
    k_fused<<<mt, 256, SMEM_REQ>>>(x, W1, b1, b2, gamma, beta, degrees,
                                   (float*)d_out, Nn);
}

// round 6
// speedup vs baseline: 2.7550x; 1.0622x over previous
#include <cuda_runtime.h>
#include <cuda_bf16.h>
#include <cstdint>

// ---------------------------------------------------------------------------
// ResidualGNNLayer (sm_103, mma.sync bf16x3):
//   k_prep / k_edge / k_feat as before; k_fused now 512 threads (16 warps,
//   warp tile 32x32) to lift occupancy 12.5% -> 25% (4 warps/SMSP).
// ---------------------------------------------------------------------------

#define DD 128
#define HH 512
#define KP 256
#define CAP 128
#define NN_MAX 50048    // 391 * 128

static __device__ int   g_is64;
static __device__ int   g_cnt[NN_MAX];
static __device__ float g_dist[NN_MAX];
static __device__ int   g_slots[NN_MAX * CAP];

static __device__ __nv_bfloat16 g_feat_hi[(size_t)NN_MAX * KP];
static __device__ __nv_bfloat16 g_feat_lo[(size_t)NN_MAX * KP];
static __device__ __nv_bfloat16 g_w1t_hi[HH * KP];     // [n=512][k=256]
static __device__ __nv_bfloat16 g_w1t_lo[HH * KP];
static __device__ __nv_bfloat16 g_w2t_hi[DD * HH];     // [n=128][k=512]
static __device__ __nv_bfloat16 g_w2t_lo[DD * HH];

// ---------------- PTX helpers ----------------------------------------------
__device__ __forceinline__ uint32_t smem_u32(const void* p) {
    uint32_t a;
    asm("{ .reg .u64 t; cvta.to.shared.u64 t, %1; cvt.u32.u64 %0, t; }"
        : "=r"(a) : "l"(p));
    return a;
}
__device__ __forceinline__ void cp16(uint32_t d, const void* s) {
    asm volatile("cp.async.ca.shared.global [%0], [%1], 16;" :: "r"(d), "l"(s));
}
#define CP_COMMIT() asm volatile("cp.async.commit_group;" ::: "memory")
#define CP_WAIT(n)  asm volatile("cp.async.wait_group %0;" :: "n"(n) : "memory")

__device__ __forceinline__ void ldm_x4(uint32_t addr, uint32_t r[4]) {
    asm volatile("ldmatrix.sync.aligned.m8n8.x4.shared.b16 {%0,%1,%2,%3}, [%4];"
                 : "=r"(r[0]), "=r"(r[1]), "=r"(r[2]), "=r"(r[3]) : "r"(addr));
}
__device__ __forceinline__ void mma16816(float d[4], const uint32_t a[4],
                                         const uint32_t b0, const uint32_t b1) {
    asm volatile(
        "mma.sync.aligned.m16n8k16.row.col.f32.bf16.bf16.f32 "
        "{%0,%1,%2,%3},{%4,%5,%6,%7},{%8,%9},{%0,%1,%2,%3};"
        : "+f"(d[0]), "+f"(d[1]), "+f"(d[2]), "+f"(d[3])
        : "r"(a[0]), "r"(a[1]), "r"(a[2]), "r"(a[3]), "r"(b0), "r"(b1));
}
__device__ __forceinline__ void split2(float a, float b,
                                       __nv_bfloat16* ph, __nv_bfloat16* pl) {
    __nv_bfloat16 ha = __float2bfloat16(a), hb = __float2bfloat16(b);
    __nv_bfloat16 la = __float2bfloat16(a - __bfloat162float(ha));
    __nv_bfloat16 lb = __float2bfloat16(b - __bfloat162float(hb));
    *(__nv_bfloat162*)ph = __halves2bfloat162(ha, hb);
    *(__nv_bfloat162*)pl = __halves2bfloat162(la, lb);
}
__device__ __forceinline__ uint32_t swz(int r, int c) {
    return (uint32_t)(r * 64 + (((((c >> 4) ^ (r >> 1)) & 3) << 4) | (c & 15)));
}

// ---------------- prep ------------------------------------------------------
__global__ void k_prep(const float* __restrict__ W1, const float* __restrict__ W2,
                       const void* __restrict__ eraw, int E, int Nn) {
    int b = blockIdx.x, t = threadIdx.x;
    if (b == 0) {
        if (t == 0) {
            const long long* p64 = (const long long*)eraw;
            int ok64 = 1;
            int step = E / 32; if (step < 1) step = 1;
            for (int i = 0; i < 32; i++) {
                long long idx = (long long)i * step;
                if (idx >= E) break;
                long long v = p64[idx];
                if (v < 0 || v >= Nn) { ok64 = 0; break; }
            }
            g_is64 = ok64;
        }
        return;
    }
    int ZB = (Nn + 255) / 256;
    if (b - 1 < ZB) {
        int i = (b - 1) * 256 + t;
        if (i < Nn) { g_cnt[i] = 0; g_dist[i] = 0.f; }
        return;
    }
    int b2 = b - 1 - ZB;
    if (b2 < (HH * KP) / 256) {
        int idx = b2 * 256 + t;
        int n = idx >> 8, k = idx & 255;
        float v = W1[k * HH + n];
        __nv_bfloat16 h = __float2bfloat16(v);
        g_w1t_hi[idx] = h;
        g_w1t_lo[idx] = __float2bfloat16(v - __bfloat162float(h));
        return;
    }
    int b3 = b2 - (HH * KP) / 256;
    int idx = b3 * 256 + t;
    int n = idx >> 9, k = idx & 511;
    float v = W2[k * DD + n];
    __nv_bfloat16 h = __float2bfloat16(v);
    g_w2t_hi[idx] = h;
    g_w2t_lo[idx] = __float2bfloat16(v - __bfloat162float(h));
}

__global__ void k_edge(const void* __restrict__ eraw,
                       const float* __restrict__ ed, int E, int Nn) {
    int e = blockIdx.x * blockDim.x + threadIdx.x;
    if (e >= E) return;
    int src, dst;
    if (g_is64) {
        const long long* p = (const long long*)eraw;
        src = (int)p[e]; dst = (int)p[E + e];
    } else {
        const int* p = (const int*)eraw;
        src = p[e]; dst = p[E + e];
    }
    src = min(max(src, 0), Nn - 1);
    dst = min(max(dst, 0), Nn - 1);
    int p = atomicAdd(&g_cnt[src], 1);
    if (p < CAP) g_slots[src * CAP + p] = dst;
    atomicAdd(&g_dist[src], ed[e]);
}

__global__ void k_feat(const float* __restrict__ x,
                       const float* __restrict__ degrees, int Nn) {
    int gw = (blockIdx.x * blockDim.x + threadIdx.x) >> 5;
    int lane = threadIdx.x & 31;
    if (gw >= Nn) return;
    int cnt = g_cnt[gw]; if (cnt > CAP) cnt = CAP;
    const int* slots = g_slots + gw * CAP;
    float4 acc = make_float4(0.f, 0.f, 0.f, 0.f);
    int dnext = (cnt > 0) ? slots[0] : 0;
    for (int j = 0; j < cnt; j++) {
        int dcur = dnext;
        if (j + 1 < cnt) dnext = slots[j + 1];
        float4 v = *(const float4*)(x + (size_t)dcur * DD + lane * 4);
        acc.x += v.x; acc.y += v.y; acc.z += v.z; acc.w += v.w;
    }
    float inv = 1.f / fmaxf(degrees[gw], 1.f);
    __nv_bfloat16* fh = g_feat_hi + (size_t)gw * KP;
    __nv_bfloat16* fl = g_feat_lo + (size_t)gw * KP;
    float4 xv = *(const float4*)(x + (size_t)gw * DD + lane * 4);
    split2(xv.x, xv.y, fh + lane * 4, fl + lane * 4);
    split2(xv.z, xv.w, fh + lane * 4 + 2, fl + lane * 4 + 2);
    split2(acc.x * inv, acc.y * inv, fh + DD + lane * 4, fl + DD + lane * 4);
    split2(acc.z * inv, acc.w * inv, fh + DD + lane * 4 + 2, fl + DD + lane * 4 + 2);
}

// ---------------------------------------------------------------------------
// Fused kernel: 512 threads, 16 warps (4x4 grid of 32x32 warp tiles).
// smem: stages[2] 32KB @0; hbuf hi @65536 lo @100352 ([128][136] bf16);
//       deg @135168, md @135680. LN reuses @0.
// ---------------------------------------------------------------------------
#define STG(s)   ((s) * 32768)
#define HB_HI    65536
#define HB_LO    100352
#define OF_DEG   135168
#define OF_MD    135680
#define OF_MUS   67584
#define OF_RSS   68096
#define SMEM_REQ 136192

struct Frags {
    uint32_t Ah[2][4], Al[2][4];
    uint32_t Bh[4][2], Bl[4][2];
};
__device__ __forceinline__ void load_B(uint32_t sbB, int wn, int lane, int ks,
                                       Frags& f) {
#pragma unroll
    for (int p = 0; p < 2; p++) {
        uint32_t addr = sbB + swz(wn * 32 + p * 16 + (lane & 15),
                                  ks * 32 + (lane >> 4) * 16);
        uint32_t r[4];
        ldm_x4(addr, r);
        f.Bh[p * 2 + 0][0] = r[0]; f.Bh[p * 2 + 0][1] = r[2];
        f.Bh[p * 2 + 1][0] = r[1]; f.Bh[p * 2 + 1][1] = r[3];
        ldm_x4(addr + 8192, r);
        f.Bl[p * 2 + 0][0] = r[0]; f.Bl[p * 2 + 0][1] = r[2];
        f.Bl[p * 2 + 1][0] = r[1]; f.Bl[p * 2 + 1][1] = r[3];
    }
}
__device__ __forceinline__ void mma_all(float acc[2][4][4], const Frags& f) {
#pragma unroll
    for (int mf = 0; mf < 2; mf++)
#pragma unroll
        for (int nf = 0; nf < 4; nf++) {
            mma16816(acc[mf][nf], f.Ah[mf], f.Bh[nf][0], f.Bh[nf][1]);
            mma16816(acc[mf][nf], f.Al[mf], f.Bh[nf][0], f.Bh[nf][1]);
            mma16816(acc[mf][nf], f.Ah[mf], f.Bl[nf][0], f.Bl[nf][1]);
        }
}

__global__ __launch_bounds__(512, 1) void k_fused(
    const float* __restrict__ x, const float* __restrict__ W1,
    const float* __restrict__ b1, const float* __restrict__ b2,
    const float* __restrict__ gamma, const float* __restrict__ beta,
    const float* __restrict__ degrees, float* __restrict__ out, int Nn) {
    extern __shared__ __align__(128) char sm[];
    uint32_t base = smem_u32(sm);
    int t = threadIdx.x, lane = t & 31, wid = t >> 5;
    int wm = wid >> 2, wn = wid & 3;
    int row0 = blockIdx.x * 128;

    float* degv = (float*)(sm + OF_DEG);
    float* mdv  = (float*)(sm + OF_MD);
    if (t < 128) {
        int gr = row0 + t;
        float dr = (gr < Nn) ? degrees[gr] : 0.f;
        float ds = (gr < Nn) ? g_dist[gr] : 0.f;
        degv[t] = dr;
        mdv[t]  = ds / fmaxf(dr, 1.f);
    }

    float acc2[2][4][4];
#pragma unroll
    for (int a = 0; a < 2; a++)
#pragma unroll
        for (int b = 0; b < 4; b++)
#pragma unroll
            for (int c = 0; c < 4; c++) acc2[a][b][c] = 0.f;

    // loader mapping: one cp16 per (thread, tile); lr=row 0..127, seg 0..3
    int lr = t >> 2, seg = (t & 3) * 16;
    const char* pAh = (const char*)(g_feat_hi + (size_t)(row0 + lr) * KP) + seg;
    const char* pAl = (const char*)(g_feat_lo + (size_t)(row0 + lr) * KP) + seg;
    uint32_t dA = base + swz(lr, seg);

#pragma unroll 1
    for (int nc = 0; nc < 4; nc++) {
        float acc1[2][4][4];
#pragma unroll
        for (int a = 0; a < 2; a++)
#pragma unroll
            for (int b = 0; b < 4; b++)
#pragma unroll
                for (int c = 0; c < 4; c++) acc1[a][b][c] = 0.f;

        const char* pBh = (const char*)(g_w1t_hi + (size_t)(nc * 128 + lr) * KP) + seg;
        const char* pBl = (const char*)(g_w1t_lo + (size_t)(nc * 128 + lr) * KP) + seg;

        // ---- GEMM1: K=256, 8 steps of BK=32 ----
#pragma unroll 1
        for (int s = 0; s < 2; s++) {
            uint32_t d = dA + STG(s);
            cp16(d, pAh + s * 64);
            cp16(d + 8192, pAl + s * 64);
            cp16(d + 16384, pBh + s * 64);
            cp16(d + 24576, pBl + s * 64);
            CP_COMMIT();
        }
#pragma unroll 1
        for (int s = 0; s < 8; s++) {
            if (s < 7) { CP_WAIT(1); } else { CP_WAIT(0); }
            __syncthreads();
            uint32_t sb = base + STG(s & 1);
#pragma unroll
            for (int ks = 0; ks < 2; ks++) {
                Frags f;
#pragma unroll
                for (int mf = 0; mf < 2; mf++) {
                    uint32_t a = sb + swz(wm * 32 + mf * 16 + (lane & 15),
                                          ks * 32 + (lane >> 4) * 16);
                    ldm_x4(a, f.Ah[mf]);
                    ldm_x4(a + 8192, f.Al[mf]);
                }
                load_B(sb + 16384, wn, lane, ks, f);
                mma_all(acc1, f);
            }
            __syncthreads();
            if (s + 2 < 8) {
                uint32_t d = dA + STG(s & 1);
                cp16(d, pAh + (s + 2) * 64);
                cp16(d + 8192, pAl + (s + 2) * 64);
                cp16(d + 16384, pBh + (s + 2) * 64);
                cp16(d + 24576, pBl + (s + 2) * 64);
                CP_COMMIT();
            }
        }

        // ---- chunk epilogue: bias + rank-2 + relu -> hbuf hi/lo ----
#pragma unroll
        for (int mf = 0; mf < 2; mf++) {
            int rl = wm * 32 + mf * 16 + (lane >> 2);
            float d0 = degv[rl], m0 = mdv[rl];
            float d1 = degv[rl + 8], m1 = mdv[rl + 8];
#pragma unroll
            for (int nf = 0; nf < 4; nf++) {
                int cl = wn * 32 + nf * 8 + (lane & 3) * 2;
                int cg = nc * 128 + cl;
                float b10 = __ldg(b1 + cg), b11 = __ldg(b1 + cg + 1);
                float wd0 = __ldg(W1 + 256 * HH + cg), wd1 = __ldg(W1 + 256 * HH + cg + 1);
                float wm0 = __ldg(W1 + 257 * HH + cg), wm1 = __ldg(W1 + 257 * HH + cg + 1);
                float v00 = fmaxf(acc1[mf][nf][0] + b10 + d0 * wd0 + m0 * wm0, 0.f);
                float v01 = fmaxf(acc1[mf][nf][1] + b11 + d0 * wd1 + m0 * wm1, 0.f);
                float v10 = fmaxf(acc1[mf][nf][2] + b10 + d1 * wd0 + m1 * wm0, 0.f);
                float v11 = fmaxf(acc1[mf][nf][3] + b11 + d1 * wd1 + m1 * wm1, 0.f);
                split2(v00, v01,
                       (__nv_bfloat16*)(sm + HB_HI + (rl * 136 + cl) * 2),
                       (__nv_bfloat16*)(sm + HB_LO + (rl * 136 + cl) * 2));
                split2(v10, v11,
                       (__nv_bfloat16*)(sm + HB_HI + ((rl + 8) * 136 + cl) * 2),
                       (__nv_bfloat16*)(sm + HB_LO + ((rl + 8) * 136 + cl) * 2));
            }
        }
        // prefetch W2 k-slices (B region of stages; 1 cp16/thread/tile)
        const char* pWh = (const char*)(g_w2t_hi + (size_t)lr * HH + nc * 128) + seg;
        const char* pWl = (const char*)(g_w2t_lo + (size_t)lr * HH + nc * 128) + seg;
#pragma unroll 1
        for (int s = 0; s < 2; s++) {
            uint32_t d = dA + STG(s);
            cp16(d + 16384, pWh + s * 64);
            cp16(d + 24576, pWl + s * 64);
            CP_COMMIT();
        }
        __syncthreads();   // hbuf visible

        // ---- GEMM2 partial: 4 steps of BK=32 over this 128-k chunk ----
#pragma unroll 1
        for (int s = 0; s < 4; s++) {
            if (s < 3) { CP_WAIT(1); } else { CP_WAIT(0); }
            __syncthreads();
            uint32_t sb = base + STG(s & 1);
#pragma unroll
            for (int ks = 0; ks < 2; ks++) {
                Frags f;
#pragma unroll
                for (int mf = 0; mf < 2; mf++) {
                    uint32_t a = base + HB_HI +
                        (uint32_t)((wm * 32 + mf * 16 + (lane & 15)) * 272 +
                                   s * 64 + ks * 32 + (lane >> 4) * 16);
                    ldm_x4(a, f.Ah[mf]);
                    ldm_x4(a + (HB_LO - HB_HI), f.Al[mf]);
                }
                load_B(sb + 16384, wn, lane, ks, f);
                mma_all(acc2, f);
            }
            __syncthreads();
            if (s + 2 < 4) {
                uint32_t d = dA + STG(s & 1);
                cp16(d + 16384, pWh + (s + 2) * 64);
                cp16(d + 24576, pWl + (s + 2) * 64);
                CP_COMMIT();
            }
        }
    }

    // ---- final epilogue: + b2 + x, LayerNorm, store ----
    float* yb  = (float*)sm;                 // [128][129]
    float* mus = (float*)(sm + OF_MUS);
    float* rss = (float*)(sm + OF_RSS);
#pragma unroll
    for (int mf = 0; mf < 2; mf++)
#pragma unroll
        for (int nf = 0; nf < 4; nf++) {
            int rl = wm * 32 + mf * 16 + (lane >> 2);
            int cc = wn * 32 + nf * 8 + (lane & 3) * 2;
            float bi0 = __ldg(b2 + cc), bi1 = __ldg(b2 + cc + 1);
            int g0 = row0 + rl, g1 = g0 + 8;
            float x00 = 0.f, x01 = 0.f, x10 = 0.f, x11 = 0.f;
            if (g0 < Nn) {
                float2 v = *(const float2*)(x + (size_t)g0 * DD + cc);
                x00 = v.x; x01 = v.y;
            }
            if (g1 < Nn) {
                float2 v = *(const float2*)(x + (size_t)g1 * DD + cc);
                x10 = v.x; x11 = v.y;
            }
            yb[rl * 129 + cc]           = acc2[mf][nf][0] + bi0 + x00;
            yb[rl * 129 + cc + 1]       = acc2[mf][nf][1] + bi1 + x01;
            yb[(rl + 8) * 129 + cc]     = acc2[mf][nf][2] + bi0 + x10;
            yb[(rl + 8) * 129 + cc + 1] = acc2[mf][nf][3] + bi1 + x11;
        }
    __syncthreads();
    if (t < 256) {
        int row = t >> 1;
        const float* r = yb + row * 129 + (t & 1) * 64;
        float s0 = 0.f, s1 = 0.f;
#pragma unroll
        for (int c = 0; c < 64; c++) { float v = r[c]; s0 += v; s1 += v * v; }
        s0 += __shfl_xor_sync(0xffffffffu, s0, 1);
        s1 += __shfl_xor_sync(0xffffffffu, s1, 1);
        if ((t & 1) == 0) {
            float mu = s0 * (1.f / 128.f);
            float var = s1 * (1.f / 128.f) - mu * mu;
            mus[row] = mu;
            rss[row] = rsqrtf(var + 1e-5f);
        }
    }
    __syncthreads();
#pragma unroll
    for (int i = 0; i < 32; i++) {
        int w = t + i * 512;
        int row = w >> 7, col = w & 127;
        int grow = row0 + row;
        if (grow < Nn) {
            float v = yb[row * 129 + col];
            out[(size_t)grow * DD + col] =
                (v - mus[row]) * rss[row] * __ldg(gamma + col) + __ldg(beta + col);
        }
    }
}

// ---------------------------------------------------------------------------
extern "C" void kernel_launch(void* const* d_in, const int* in_sizes, int n_in,
                              void* d_out, int out_size) {
    const float* x       = (const float*)d_in[0];
    const float* W1      = (const float*)d_in[1];
    const float* b1      = (const float*)d_in[2];
    const float* W2      = (const float*)d_in[3];
    const float* b2      = (const float*)d_in[4];
    const float* gamma   = (const float*)d_in[5];
    const float* beta    = (const float*)d_in[6];
    const void*  ei      = d_in[7];
    const float* ed      = (const float*)d_in[8];
    const float* degrees = (const float*)d_in[9];

    int Nn = in_sizes[0] / DD;
    int E  = in_sizes[8];

    cudaFuncSetAttribute(k_fused, cudaFuncAttributeMaxDynamicSharedMemorySize,
                         SMEM_REQ);

    int ZB = (Nn + 255) / 256;
    int prep_blocks = 1 + ZB + (HH * KP) / 256 + (DD * HH) / 256;
    k_prep<<<prep_blocks, 256>>>(W1, W2, ei, E, Nn);
    k_edge<<<(E + 255) / 256, 256>>>(ei, ed, E, Nn);
    k_feat<<<(Nn + 7) / 8, 256>>>(x, degrees, Nn);

    int mt = (Nn + 127) / 128;  // 391
    k_fused<<<mt, 512, SMEM_REQ>>>(x, W1, b1, b2, gamma, beta, degrees,
                                   (float*)d_out, Nn);
}

// round 7
// speedup vs baseline: 3.5181x; 1.2770x over previous
#include <cuda_runtime.h>
#include <cuda_fp16.h>
#include <cstdint>

// ---------------------------------------------------------------------------
// ResidualGNNLayer (sm_103, mma.sync fp16 2-term split):
//   feat/h in fp16 hi/lo (A side exact to 2^-22), weights fp16 hi only
//   (rounding err ~2^-12).  GEMM cores: 512 thr, 16 warps 32x32, BK=32,
//   3-stage cp.async pipeline, ONE __syncthreads per k-step.
// ---------------------------------------------------------------------------

#define DD 128
#define HH 512
#define KP 256
#define CAP 128
#define NN_MAX 50048    // 391 * 128

static __device__ int   g_is64;
static __device__ int   g_cnt[NN_MAX];
static __device__ float g_dist[NN_MAX];
static __device__ int   g_slots[NN_MAX * CAP];

static __device__ __half g_feat_hi[(size_t)NN_MAX * KP];
static __device__ __half g_feat_lo[(size_t)NN_MAX * KP];
static __device__ __half g_w1t[HH * KP];     // [n=512][k=256]
static __device__ __half g_w2t[DD * HH];     // [n=128][k=512]

// ---------------- PTX helpers ----------------------------------------------
__device__ __forceinline__ uint32_t smem_u32(const void* p) {
    uint32_t a;
    asm("{ .reg .u64 t; cvta.to.shared.u64 t, %1; cvt.u32.u64 %0, t; }"
        : "=r"(a) : "l"(p));
    return a;
}
__device__ __forceinline__ void cp16(uint32_t d, const void* s) {
    asm volatile("cp.async.ca.shared.global [%0], [%1], 16;" :: "r"(d), "l"(s));
}
#define CP_COMMIT() asm volatile("cp.async.commit_group;" ::: "memory")
#define CP_WAIT(n)  asm volatile("cp.async.wait_group %0;" :: "n"(n) : "memory")

__device__ __forceinline__ void ldm_x4(uint32_t addr, uint32_t r[4]) {
    asm volatile("ldmatrix.sync.aligned.m8n8.x4.shared.b16 {%0,%1,%2,%3}, [%4];"
                 : "=r"(r[0]), "=r"(r[1]), "=r"(r[2]), "=r"(r[3]) : "r"(addr));
}
__device__ __forceinline__ void mma16816(float d[4], const uint32_t a[4],
                                         const uint32_t b0, const uint32_t b1) {
    asm volatile(
        "mma.sync.aligned.m16n8k16.row.col.f32.f16.f16.f32 "
        "{%0,%1,%2,%3},{%4,%5,%6,%7},{%8,%9},{%0,%1,%2,%3};"
        : "+f"(d[0]), "+f"(d[1]), "+f"(d[2]), "+f"(d[3])
        : "r"(a[0]), "r"(a[1]), "r"(a[2]), "r"(a[3]), "r"(b0), "r"(b1));
}
__device__ __forceinline__ void split2(float a, float b, __half* ph, __half* pl) {
    __half ha = __float2half_rn(a), hb = __float2half_rn(b);
    __half la = __float2half_rn(a - __half2float(ha));
    __half lb = __float2half_rn(b - __half2float(hb));
    *(__half2*)ph = __halves2half2(ha, hb);
    *(__half2*)pl = __halves2half2(la, lb);
}
__device__ __forceinline__ uint32_t swz(int r, int c) {
    return (uint32_t)(r * 64 + (((((c >> 4) ^ (r >> 1)) & 3) << 4) | (c & 15)));
}

// ---------------- prep ------------------------------------------------------
__global__ void k_prep(const float* __restrict__ W1, const float* __restrict__ W2,
                       const void* __restrict__ eraw, int E, int Nn) {
    int b = blockIdx.x, t = threadIdx.x;
    if (b == 0) {
        if (t == 0) {
            const long long* p64 = (const long long*)eraw;
            int ok64 = 1;
            int step = E / 32; if (step < 1) step = 1;
            for (int i = 0; i < 32; i++) {
                long long idx = (long long)i * step;
                if (idx >= E) break;
                long long v = p64[idx];
                if (v < 0 || v >= Nn) { ok64 = 0; break; }
            }
            g_is64 = ok64;
        }
        return;
    }
    int ZB = (Nn + 255) / 256;
    if (b - 1 < ZB) {
        int i = (b - 1) * 256 + t;
        if (i < Nn) { g_cnt[i] = 0; g_dist[i] = 0.f; }
        return;
    }
    int b2 = b - 1 - ZB;
    if (b2 < (HH * KP) / 256) {
        int idx = b2 * 256 + t;
        int n = idx >> 8, k = idx & 255;
        g_w1t[idx] = __float2half_rn(W1[k * HH + n]);
        return;
    }
    int b3 = b2 - (HH * KP) / 256;
    int idx = b3 * 256 + t;
    int n = idx >> 9, k = idx & 511;
    g_w2t[idx] = __float2half_rn(W2[k * DD + n]);
}

__global__ void k_edge(const void* __restrict__ eraw,
                       const float* __restrict__ ed, int E, int Nn) {
    int e = blockIdx.x * blockDim.x + threadIdx.x;
    if (e >= E) return;
    int src, dst;
    if (g_is64) {
        const long long* p = (const long long*)eraw;
        src = (int)p[e]; dst = (int)p[E + e];
    } else {
        const int* p = (const int*)eraw;
        src = p[e]; dst = p[E + e];
    }
    src = min(max(src, 0), Nn - 1);
    dst = min(max(dst, 0), Nn - 1);
    int p = atomicAdd(&g_cnt[src], 1);
    if (p < CAP) g_slots[src * CAP + p] = dst;
    atomicAdd(&g_dist[src], ed[e]);
}

__global__ void k_feat(const float* __restrict__ x,
                       const float* __restrict__ degrees, int Nn) {
    int gw = (blockIdx.x * blockDim.x + threadIdx.x) >> 5;
    int lane = threadIdx.x & 31;
    if (gw >= Nn) return;
    int cnt = g_cnt[gw]; if (cnt > CAP) cnt = CAP;
    const int* slots = g_slots + gw * CAP;
    float4 acc = make_float4(0.f, 0.f, 0.f, 0.f);
    int dnext = (cnt > 0) ? slots[0] : 0;
    for (int j = 0; j < cnt; j++) {
        int dcur = dnext;
        if (j + 1 < cnt) dnext = slots[j + 1];
        float4 v = *(const float4*)(x + (size_t)dcur * DD + lane * 4);
        acc.x += v.x; acc.y += v.y; acc.z += v.z; acc.w += v.w;
    }
    float inv = 1.f / fmaxf(degrees[gw], 1.f);
    __half* fh = g_feat_hi + (size_t)gw * KP;
    __half* fl = g_feat_lo + (size_t)gw * KP;
    float4 xv = *(const float4*)(x + (size_t)gw * DD + lane * 4);
    split2(xv.x, xv.y, fh + lane * 4, fl + lane * 4);
    split2(xv.z, xv.w, fh + lane * 4 + 2, fl + lane * 4 + 2);
    split2(acc.x * inv, acc.y * inv, fh + DD + lane * 4, fl + DD + lane * 4);
    split2(acc.z * inv, acc.w * inv, fh + DD + lane * 4 + 2, fl + DD + lane * 4 + 2);
}

// ---------------------------------------------------------------------------
// smem: 3 stages of 24KB @0 (Ah +0, Al +8192, Bh +16384);
//       hbuf hi @73728 lo @108544 ([128][136] fp16); deg @143360, md @143872.
//       LN: yb f32 [128][129] @0, mus @66048, rss @66560.
// ---------------------------------------------------------------------------
#define STG(s)   ((s) * 24576)
#define HB_HI    73728
#define HB_LO    108544
#define OF_DEG   143360
#define OF_MD    143872
#define OF_MUS   66048
#define OF_RSS   66560
#define SMEM_REQ 144384

struct Frags {
    uint32_t Ah[2][4], Al[2][4];
    uint32_t Bh[4][2];
};
__device__ __forceinline__ void load_B(uint32_t sbB, int wn, int lane, int ks,
                                       Frags& f) {
#pragma unroll
    for (int p = 0; p < 2; p++) {
        uint32_t addr = sbB + swz(wn * 32 + p * 16 + (lane & 15),
                                  ks * 32 + (lane >> 4) * 16);
        uint32_t r[4];
        ldm_x4(addr, r);
        f.Bh[p * 2 + 0][0] = r[0]; f.Bh[p * 2 + 0][1] = r[2];
        f.Bh[p * 2 + 1][0] = r[1]; f.Bh[p * 2 + 1][1] = r[3];
    }
}
__device__ __forceinline__ void mma_all(float acc[2][4][4], const Frags& f) {
#pragma unroll
    for (int mf = 0; mf < 2; mf++)
#pragma unroll
        for (int nf = 0; nf < 4; nf++) {
            mma16816(acc[mf][nf], f.Ah[mf], f.Bh[nf][0], f.Bh[nf][1]);
            mma16816(acc[mf][nf], f.Al[mf], f.Bh[nf][0], f.Bh[nf][1]);
        }
}

__global__ __launch_bounds__(512, 1) void k_fused(
    const float* __restrict__ x, const float* __restrict__ W1,
    const float* __restrict__ b1, const float* __restrict__ b2,
    const float* __restrict__ gamma, const float* __restrict__ beta,
    const float* __restrict__ degrees, float* __restrict__ out, int Nn) {
    extern __shared__ __align__(128) char sm[];
    uint32_t base = smem_u32(sm);
    int t = threadIdx.x, lane = t & 31, wid = t >> 5;
    int wm = wid >> 2, wn = wid & 3;
    int row0 = blockIdx.x * 128;

    float* degv = (float*)(sm + OF_DEG);
    float* mdv  = (float*)(sm + OF_MD);
    if (t < 128) {
        int gr = row0 + t;
        float dr = (gr < Nn) ? degrees[gr] : 0.f;
        float ds = (gr < Nn) ? g_dist[gr] : 0.f;
        degv[t] = dr;
        mdv[t]  = ds / fmaxf(dr, 1.f);
    }

    float acc2[2][4][4];
#pragma unroll
    for (int a = 0; a < 2; a++)
#pragma unroll
        for (int b = 0; b < 4; b++)
#pragma unroll
            for (int c = 0; c < 4; c++) acc2[a][b][c] = 0.f;

    // loader mapping: lr = row 0..127, seg = 16B segment 0..3
    int lr = t >> 2, seg = (t & 3) * 16;
    const char* pAh = (const char*)(g_feat_hi + (size_t)(row0 + lr) * KP) + seg;
    const char* pAl = (const char*)(g_feat_lo + (size_t)(row0 + lr) * KP) + seg;
    uint32_t dA = base + swz(lr, seg);

#pragma unroll 1
    for (int nc = 0; nc < 4; nc++) {
        float acc1[2][4][4];
#pragma unroll
        for (int a = 0; a < 2; a++)
#pragma unroll
            for (int b = 0; b < 4; b++)
#pragma unroll
                for (int c = 0; c < 4; c++) acc1[a][b][c] = 0.f;

        const char* pBh = (const char*)(g_w1t + (size_t)(nc * 128 + lr) * KP) + seg;

        // ---- GEMM1: K=256, 8 steps of BK=32, 3-stage pipe, 1 sync/step ----
#pragma unroll 1
        for (int s = 0; s < 2; s++) {
            uint32_t d = dA + STG(s);
            cp16(d, pAh + s * 64);
            cp16(d + 8192, pAl + s * 64);
            cp16(d + 16384, pBh + s * 64);
            CP_COMMIT();
        }
#pragma unroll 1
        for (int s = 0; s < 8; s++) {
            if (s < 7) { CP_WAIT(1); } else { CP_WAIT(0); }
            __syncthreads();
            if (s + 2 < 8) {
                uint32_t d = dA + STG((s + 2) % 3);
                cp16(d, pAh + (s + 2) * 64);
                cp16(d + 8192, pAl + (s + 2) * 64);
                cp16(d + 16384, pBh + (s + 2) * 64);
                CP_COMMIT();
            }
            uint32_t sb = base + STG(s % 3);
#pragma unroll
            for (int ks = 0; ks < 2; ks++) {
                Frags f;
#pragma unroll
                for (int mf = 0; mf < 2; mf++) {
                    uint32_t a = sb + swz(wm * 32 + mf * 16 + (lane & 15),
                                          ks * 32 + (lane >> 4) * 16);
                    ldm_x4(a, f.Ah[mf]);
                    ldm_x4(a + 8192, f.Al[mf]);
                }
                load_B(sb + 16384, wn, lane, ks, f);
                mma_all(acc1, f);
            }
        }
        __syncthreads();   // all warps done reading GEMM1 stages

        // W2 slices for this chunk: preload stages 0,1
        const char* pWh = (const char*)(g_w2t + (size_t)lr * HH + nc * 128) + seg;
#pragma unroll 1
        for (int s = 0; s < 2; s++) {
            cp16(dA + STG(s) + 16384, pWh + s * 64);
            CP_COMMIT();
        }

        // ---- chunk epilogue: bias + rank-2 + relu -> hbuf hi/lo ----
#pragma unroll
        for (int mf = 0; mf < 2; mf++) {
            int rl = wm * 32 + mf * 16 + (lane >> 2);
            float d0 = degv[rl], m0 = mdv[rl];
            float d1 = degv[rl + 8], m1 = mdv[rl + 8];
#pragma unroll
            for (int nf = 0; nf < 4; nf++) {
                int cl = wn * 32 + nf * 8 + (lane & 3) * 2;
                int cg = nc * 128 + cl;
                float b10 = __ldg(b1 + cg), b11 = __ldg(b1 + cg + 1);
                float wd0 = __ldg(W1 + 256 * HH + cg), wd1 = __ldg(W1 + 256 * HH + cg + 1);
                float wm0 = __ldg(W1 + 257 * HH + cg), wm1 = __ldg(W1 + 257 * HH + cg + 1);
                float v00 = fmaxf(acc1[mf][nf][0] + b10 + d0 * wd0 + m0 * wm0, 0.f);
                float v01 = fmaxf(acc1[mf][nf][1] + b11 + d0 * wd1 + m0 * wm1, 0.f);
                float v10 = fmaxf(acc1[mf][nf][2] + b10 + d1 * wd0 + m1 * wm0, 0.f);
                float v11 = fmaxf(acc1[mf][nf][3] + b11 + d1 * wd1 + m1 * wm1, 0.f);
                split2(v00, v01,
                       (__half*)(sm + HB_HI + (rl * 136 + cl) * 2),
                       (__half*)(sm + HB_LO + (rl * 136 + cl) * 2));
                split2(v10, v11,
                       (__half*)(sm + HB_HI + ((rl + 8) * 136 + cl) * 2),
                       (__half*)(sm + HB_LO + ((rl + 8) * 136 + cl) * 2));
            }
        }
        __syncthreads();   // hbuf visible

        // ---- GEMM2 partial: 4 steps of BK=32 over this 128-k chunk ----
#pragma unroll 1
        for (int s = 0; s < 4; s++) {
            if (s < 3) { CP_WAIT(1); } else { CP_WAIT(0); }
            __syncthreads();
            if (s + 2 < 4) {
                cp16(dA + STG((s + 2) % 3) + 16384, pWh + (s + 2) * 64);
                CP_COMMIT();
            }
            uint32_t sb = base + STG(s % 3);
#pragma unroll
            for (int ks = 0; ks < 2; ks++) {
                Frags f;
#pragma unroll
                for (int mf = 0; mf < 2; mf++) {
                    uint32_t a = base + HB_HI +
                        (uint32_t)((wm * 32 + mf * 16 + (lane & 15)) * 272 +
                                   s * 64 + ks * 32 + (lane >> 4) * 16);
                    ldm_x4(a, f.Ah[mf]);
                    ldm_x4(a + (HB_LO - HB_HI), f.Al[mf]);
                }
                load_B(sb + 16384, wn, lane, ks, f);
                mma_all(acc2, f);
            }
        }
        __syncthreads();   // stages + hbuf reusable next chunk
    }

    // ---- final epilogue: + b2 + x, LayerNorm, store ----
    float* yb  = (float*)sm;                 // [128][129]
    float* mus = (float*)(sm + OF_MUS);
    float* rss = (float*)(sm + OF_RSS);
#pragma unroll
    for (int mf = 0; mf < 2; mf++)
#pragma unroll
        for (int nf = 0; nf < 4; nf++) {
            int rl = wm * 32 + mf * 16 + (lane >> 2);
            int cc = wn * 32 + nf * 8 + (lane & 3) * 2;
            float bi0 = __ldg(b2 + cc), bi1 = __ldg(b2 + cc + 1);
            int g0 = row0 + rl, g1 = g0 + 8;
            float x00 = 0.f, x01 = 0.f, x10 = 0.f, x11 = 0.f;
            if (g0 < Nn) {
                float2 v = *(const float2*)(x + (size_t)g0 * DD + cc);
                x00 = v.x; x01 = v.y;
            }
            if (g1 < Nn) {
                float2 v = *(const float2*)(x + (size_t)g1 * DD + cc);
                x10 = v.x; x11 = v.y;
            }
            yb[rl * 129 + cc]           = acc2[mf][nf][0] + bi0 + x00;
            yb[rl * 129 + cc + 1]       = acc2[mf][nf][1] + bi1 + x01;
            yb[(rl + 8) * 129 + cc]     = acc2[mf][nf][2] + bi0 + x10;
            yb[(rl + 8) * 129 + cc + 1] = acc2[mf][nf][3] + bi1 + x11;
        }
    __syncthreads();
    if (t < 256) {
        int row = t >> 1;
        const float* r = yb + row * 129 + (t & 1) * 64;
        float s0 = 0.f, s1 = 0.f;
#pragma unroll
        for (int c = 0; c < 64; c++) { float v = r[c]; s0 += v; s1 += v * v; }
        s0 += __shfl_xor_sync(0xffffffffu, s0, 1);
        s1 += __shfl_xor_sync(0xffffffffu, s1, 1);
        if ((t & 1) == 0) {
            float mu = s0 * (1.f / 128.f);
            float var = s1 * (1.f / 128.f) - mu * mu;
            mus[row] = mu;
            rss[row] = rsqrtf(var + 1e-5f);
        }
    }
    __syncthreads();
#pragma unroll
    for (int i = 0; i < 32; i++) {
        int w = t + i * 512;
        int row = w >> 7, col = w & 127;
        int grow = row0 + row;
        if (grow < Nn) {
            float v = yb[row * 129 + col];
            out[(size_t)grow * DD + col] =
                (v - mus[row]) * rss[row] * __ldg(gamma + col) + __ldg(beta + col);
        }
    }
}

// ---------------------------------------------------------------------------
extern "C" void kernel_launch(void* const* d_in, const int* in_sizes, int n_in,
                              void* d_out, int out_size) {
    const float* x       = (const float*)d_in[0];
    const float* W1      = (const float*)d_in[1];
    const float* b1      = (const float*)d_in[2];
    const float* W2      = (const float*)d_in[3];
    const float* b2      = (const float*)d_in[4];
    const float* gamma   = (const float*)d_in[5];
    const float* beta    = (const float*)d_in[6];
    const void*  ei      = d_in[7];
    const float* ed      = (const float*)d_in[8];
    const float* degrees = (const float*)d_in[9];

    int Nn = in_sizes[0] / DD;
    int E  = in_sizes[8];

    cudaFuncSetAttribute(k_fused, cudaFuncAttributeMaxDynamicSharedMemorySize,
                         SMEM_REQ);

    int ZB = (Nn + 255) / 256;
    int prep_blocks = 1 + ZB + (HH * KP) / 256 + (DD * HH) / 256;
    k_prep<<<prep_blocks, 256>>>(W1, W2, ei, E, Nn);
    k_edge<<<(E + 255) / 256, 256>>>(ei, ed, E, Nn);
    k_feat<<<(Nn + 7) / 8, 256>>>(x, degrees, Nn);

    int mt = (Nn + 127) / 128;  // 391
    k_fused<<<mt, 512, SMEM_REQ>>>(x, W1, b1, b2, gamma, beta, degrees,
                                   (float*)d_out, Nn);
}

// round 8
// speedup vs baseline: 4.5791x; 1.3016x over previous
#include <cuda_runtime.h>
#include <cuda_fp16.h>
#include <cstdint>

// ---------------------------------------------------------------------------
// ResidualGNNLayer (sm_103, single-term fp16 mma.sync):
//   x -> fp16 once; warp-per-node gather-mean in fp16 -> feat fp16 (K=256)
//   fused: GEMM1(K=256)+bias+rank2(deg,md)+relu -> h fp16 in smem
//          -> GEMM2(K=512) + residual + LayerNorm
//   512 thr / 16 warps 32x32, BK=32, 3-stage cp.async, 1 sync per k-step.
// ---------------------------------------------------------------------------

#define DD 128
#define HH 512
#define KP 256
#define CAP 128
#define NN_MAX 50048    // 391 * 128

static __device__ int   g_is64;
static __device__ int   g_cnt[NN_MAX];
static __device__ float g_dist[NN_MAX];
static __device__ int   g_slots[NN_MAX * CAP];

static __device__ __half g_xh[(size_t)NN_MAX * DD];   // fp16 copy of x
static __device__ __half g_feat[(size_t)NN_MAX * KP];
static __device__ __half g_w1t[HH * KP];              // [n=512][k=256]
static __device__ __half g_w2t[DD * HH];              // [n=128][k=512]

// ---------------- PTX helpers ----------------------------------------------
__device__ __forceinline__ uint32_t smem_u32(const void* p) {
    uint32_t a;
    asm("{ .reg .u64 t; cvta.to.shared.u64 t, %1; cvt.u32.u64 %0, t; }"
        : "=r"(a) : "l"(p));
    return a;
}
__device__ __forceinline__ void cp16(uint32_t d, const void* s) {
    asm volatile("cp.async.ca.shared.global [%0], [%1], 16;" :: "r"(d), "l"(s));
}
#define CP_COMMIT() asm volatile("cp.async.commit_group;" ::: "memory")
#define CP_WAIT(n)  asm volatile("cp.async.wait_group %0;" :: "n"(n) : "memory")

__device__ __forceinline__ void ldm_x4(uint32_t addr, uint32_t r[4]) {
    asm volatile("ldmatrix.sync.aligned.m8n8.x4.shared.b16 {%0,%1,%2,%3}, [%4];"
                 : "=r"(r[0]), "=r"(r[1]), "=r"(r[2]), "=r"(r[3]) : "r"(addr));
}
__device__ __forceinline__ void mma16816(float d[4], const uint32_t a[4],
                                         const uint32_t b0, const uint32_t b1) {
    asm volatile(
        "mma.sync.aligned.m16n8k16.row.col.f32.f16.f16.f32 "
        "{%0,%1,%2,%3},{%4,%5,%6,%7},{%8,%9},{%0,%1,%2,%3};"
        : "+f"(d[0]), "+f"(d[1]), "+f"(d[2]), "+f"(d[3])
        : "r"(a[0]), "r"(a[1]), "r"(a[2]), "r"(a[3]), "r"(b0), "r"(b1));
}
__device__ __forceinline__ uint32_t swz(int r, int c) {
    return (uint32_t)(r * 64 + (((((c >> 4) ^ (r >> 1)) & 3) << 4) | (c & 15)));
}

// ---------------- prep: detect + zero + W split + x->fp16 -------------------
__global__ void k_prep(const float* __restrict__ W1, const float* __restrict__ W2,
                       const float* __restrict__ x,
                       const void* __restrict__ eraw, int E, int Nn) {
    int b = blockIdx.x, t = threadIdx.x;
    if (b == 0) {
        if (t == 0) {
            const long long* p64 = (const long long*)eraw;
            int ok64 = 1;
            int step = E / 32; if (step < 1) step = 1;
            for (int i = 0; i < 32; i++) {
                long long idx = (long long)i * step;
                if (idx >= E) break;
                long long v = p64[idx];
                if (v < 0 || v >= Nn) { ok64 = 0; break; }
            }
            g_is64 = ok64;
        }
        return;
    }
    int ZB = (Nn + 255) / 256;
    if (b - 1 < ZB) {
        int i = (b - 1) * 256 + t;
        if (i < Nn) { g_cnt[i] = 0; g_dist[i] = 0.f; }
        return;
    }
    int b2 = b - 1 - ZB;
    if (b2 < (HH * KP) / 256) {
        int idx = b2 * 256 + t;
        int n = idx >> 8, k = idx & 255;
        g_w1t[idx] = __float2half_rn(W1[k * HH + n]);
        return;
    }
    int b3 = b2 - (HH * KP) / 256;
    if (b3 < (DD * HH) / 256) {
        int idx = b3 * 256 + t;
        int n = idx >> 9, k = idx & 511;
        g_w2t[idx] = __float2half_rn(W2[k * DD + n]);
        return;
    }
    int b4 = b3 - (DD * HH) / 256;
    int idx = b4 * 256 + t;
    if (idx < Nn * DD) g_xh[idx] = __float2half_rn(x[idx]);
}

__global__ void k_edge(const void* __restrict__ eraw,
                       const float* __restrict__ ed, int E, int Nn) {
    int e = blockIdx.x * blockDim.x + threadIdx.x;
    if (e >= E) return;
    int src, dst;
    if (g_is64) {
        const long long* p = (const long long*)eraw;
        src = (int)p[e]; dst = (int)p[E + e];
    } else {
        const int* p = (const int*)eraw;
        src = p[e]; dst = p[E + e];
    }
    src = min(max(src, 0), Nn - 1);
    dst = min(max(dst, 0), Nn - 1);
    int p = atomicAdd(&g_cnt[src], 1);
    if (p < CAP) g_slots[src * CAP + p] = dst;
    atomicAdd(&g_dist[src], ed[e]);
}

// warp per node: fp16 gather + fp32 mean -> feat fp16 row [x | agg]
__global__ void k_feat(const float* __restrict__ degrees, int Nn) {
    int gw = (blockIdx.x * blockDim.x + threadIdx.x) >> 5;
    int lane = threadIdx.x & 31;
    if (gw >= Nn) return;
    int cnt = g_cnt[gw]; if (cnt > CAP) cnt = CAP;
    const int* slots = g_slots + gw * CAP;
    float4 acc = make_float4(0.f, 0.f, 0.f, 0.f);
    int dnext = (cnt > 0) ? slots[0] : 0;
    for (int j = 0; j < cnt; j++) {
        int dcur = dnext;
        if (j + 1 < cnt) dnext = slots[j + 1];
        uint2 u = *(const uint2*)(g_xh + (size_t)dcur * DD + lane * 4);
        float2 f01 = __half22float2(*(__half2*)&u.x);
        float2 f23 = __half22float2(*(__half2*)&u.y);
        acc.x += f01.x; acc.y += f01.y; acc.z += f23.x; acc.w += f23.y;
    }
    float inv = 1.f / fmaxf(degrees[gw], 1.f);
    __half* f = g_feat + (size_t)gw * KP;
    // self features: already fp16, copy
    *(uint2*)(f + lane * 4) = *(const uint2*)(g_xh + (size_t)gw * DD + lane * 4);
    __half2 a01 = __floats2half2_rn(acc.x * inv, acc.y * inv);
    __half2 a23 = __floats2half2_rn(acc.z * inv, acc.w * inv);
    *(__half2*)(f + DD + lane * 4) = a01;
    *(__half2*)(f + DD + lane * 4 + 2) = a23;
}

// ---------------------------------------------------------------------------
// smem: 3 stages of 16KB @0 (A +0, B +8192);
//       hbuf [128][136] fp16 @49152 (34816B, dead at LN);
//       deg @84480, md @84992;  LN: yb f32 [128][129] @0, mus/rss @66048/66560.
// ---------------------------------------------------------------------------
#define STG(s)   ((s) * 16384)
#define HB       49152
#define OF_MUS   66048
#define OF_RSS   66560
#define OF_DEG   84480
#define OF_MD    84992
#define SMEM_REQ 85504

struct Frags {
    uint32_t Ah[2][4];
    uint32_t Bh[4][2];
};
__device__ __forceinline__ void load_B(uint32_t sbB, int wn, int lane, int ks,
                                       Frags& f) {
#pragma unroll
    for (int p = 0; p < 2; p++) {
        uint32_t addr = sbB + swz(wn * 32 + p * 16 + (lane & 15),
                                  ks * 32 + (lane >> 4) * 16);
        uint32_t r[4];
        ldm_x4(addr, r);
        f.Bh[p * 2 + 0][0] = r[0]; f.Bh[p * 2 + 0][1] = r[2];
        f.Bh[p * 2 + 1][0] = r[1]; f.Bh[p * 2 + 1][1] = r[3];
    }
}
__device__ __forceinline__ void mma_all(float acc[2][4][4], const Frags& f) {
#pragma unroll
    for (int mf = 0; mf < 2; mf++)
#pragma unroll
        for (int nf = 0; nf < 4; nf++)
            mma16816(acc[mf][nf], f.Ah[mf], f.Bh[nf][0], f.Bh[nf][1]);
}

__global__ __launch_bounds__(512, 1) void k_fused(
    const float* __restrict__ x, const float* __restrict__ W1,
    const float* __restrict__ b1, const float* __restrict__ b2,
    const float* __restrict__ gamma, const float* __restrict__ beta,
    const float* __restrict__ degrees, float* __restrict__ out, int Nn) {
    extern __shared__ __align__(128) char sm[];
    uint32_t base = smem_u32(sm);
    int t = threadIdx.x, lane = t & 31, wid = t >> 5;
    int wm = wid >> 2, wn = wid & 3;
    int row0 = blockIdx.x * 128;

    float* degv = (float*)(sm + OF_DEG);
    float* mdv  = (float*)(sm + OF_MD);
    if (t < 128) {
        int gr = row0 + t;
        float dr = (gr < Nn) ? degrees[gr] : 0.f;
        float ds = (gr < Nn) ? g_dist[gr] : 0.f;
        degv[t] = dr;
        mdv[t]  = ds / fmaxf(dr, 1.f);
    }

    float acc2[2][4][4];
#pragma unroll
    for (int a = 0; a < 2; a++)
#pragma unroll
        for (int b = 0; b < 4; b++)
#pragma unroll
            for (int c = 0; c < 4; c++) acc2[a][b][c] = 0.f;

    // loader mapping: lr = row 0..127, seg = 16B segment 0..3 (8KB/buffer)
    int lr = t >> 2, seg = (t & 3) * 16;
    const char* pA = (const char*)(g_feat + (size_t)(row0 + lr) * KP) + seg;
    uint32_t dA = base + swz(lr, seg);

#pragma unroll 1
    for (int nc = 0; nc < 4; nc++) {
        float acc1[2][4][4];
#pragma unroll
        for (int a = 0; a < 2; a++)
#pragma unroll
            for (int b = 0; b < 4; b++)
#pragma unroll
                for (int c = 0; c < 4; c++) acc1[a][b][c] = 0.f;

        const char* pB = (const char*)(g_w1t + (size_t)(nc * 128 + lr) * KP) + seg;

        // ---- GEMM1: K=256, 8 steps of BK=32, 3-stage pipe ----
#pragma unroll 1
        for (int s = 0; s < 2; s++) {
            uint32_t d = dA + STG(s);
            cp16(d, pA + s * 64);
            cp16(d + 8192, pB + s * 64);
            CP_COMMIT();
        }
#pragma unroll 1
        for (int s = 0; s < 8; s++) {
            if (s < 7) { CP_WAIT(1); } else { CP_WAIT(0); }
            __syncthreads();
            if (s + 2 < 8) {
                uint32_t d = dA + STG((s + 2) % 3);
                cp16(d, pA + (s + 2) * 64);
                cp16(d + 8192, pB + (s + 2) * 64);
                CP_COMMIT();
            }
            uint32_t sb = base + STG(s % 3);
#pragma unroll
            for (int ks = 0; ks < 2; ks++) {
                Frags f;
#pragma unroll
                for (int mf = 0; mf < 2; mf++)
                    ldm_x4(sb + swz(wm * 32 + mf * 16 + (lane & 15),
                                    ks * 32 + (lane >> 4) * 16), f.Ah[mf]);
                load_B(sb + 8192, wn, lane, ks, f);
                mma_all(acc1, f);
            }
        }
        __syncthreads();   // GEMM1 stages free

        // W2 slices for this chunk: preload stages 0,1 (B region only)
        const char* pW = (const char*)(g_w2t + (size_t)lr * HH + nc * 128) + seg;
#pragma unroll 1
        for (int s = 0; s < 2; s++) {
            cp16(dA + STG(s) + 8192, pW + s * 64);
            CP_COMMIT();
        }

        // ---- chunk epilogue: bias + rank-2 + relu -> hbuf fp16 ----
#pragma unroll
        for (int mf = 0; mf < 2; mf++) {
            int rl = wm * 32 + mf * 16 + (lane >> 2);
            float d0 = degv[rl], m0 = mdv[rl];
            float d1 = degv[rl + 8], m1 = mdv[rl + 8];
#pragma unroll
            for (int nf = 0; nf < 4; nf++) {
                int cl = wn * 32 + nf * 8 + (lane & 3) * 2;
                int cg = nc * 128 + cl;
                float b10 = __ldg(b1 + cg), b11 = __ldg(b1 + cg + 1);
                float wd0 = __ldg(W1 + 256 * HH + cg), wd1 = __ldg(W1 + 256 * HH + cg + 1);
                float wm0 = __ldg(W1 + 257 * HH + cg), wm1 = __ldg(W1 + 257 * HH + cg + 1);
                float v00 = fmaxf(acc1[mf][nf][0] + b10 + d0 * wd0 + m0 * wm0, 0.f);
                float v01 = fmaxf(acc1[mf][nf][1] + b11 + d0 * wd1 + m0 * wm1, 0.f);
                float v10 = fmaxf(acc1[mf][nf][2] + b10 + d1 * wd0 + m1 * wm0, 0.f);
                float v11 = fmaxf(acc1[mf][nf][3] + b11 + d1 * wd1 + m1 * wm1, 0.f);
                *(__half2*)(sm + HB + (rl * 136 + cl) * 2) = __floats2half2_rn(v00, v01);
                *(__half2*)(sm + HB + ((rl + 8) * 136 + cl) * 2) = __floats2half2_rn(v10, v11);
            }
        }
        __syncthreads();   // hbuf visible

        // ---- GEMM2 partial: 4 steps of BK=32 over this 128-k chunk ----
#pragma unroll 1
        for (int s = 0; s < 4; s++) {
            if (s < 3) { CP_WAIT(1); } else { CP_WAIT(0); }
            __syncthreads();
            if (s + 2 < 4) {
                cp16(dA + STG((s + 2) % 3) + 8192, pW + (s + 2) * 64);
                CP_COMMIT();
            }
            uint32_t sb = base + STG(s % 3);
#pragma unroll
            for (int ks = 0; ks < 2; ks++) {
                Frags f;
#pragma unroll
                for (int mf = 0; mf < 2; mf++)
                    ldm_x4(base + HB +
                           (uint32_t)((wm * 32 + mf * 16 + (lane & 15)) * 272 +
                                      s * 64 + ks * 32 + (lane >> 4) * 16),
                           f.Ah[mf]);
                load_B(sb + 8192, wn, lane, ks, f);
                mma_all(acc2, f);
            }
        }
        __syncthreads();   // stages + hbuf reusable next chunk
    }

    // ---- final epilogue: + b2 + x, LayerNorm, store ----
    float* yb  = (float*)sm;                 // [128][129] (overlaps dead stages/hbuf)
    float* mus = (float*)(sm + OF_MUS);
    float* rss = (float*)(sm + OF_RSS);
#pragma unroll
    for (int mf = 0; mf < 2; mf++)
#pragma unroll
        for (int nf = 0; nf < 4; nf++) {
            int rl = wm * 32 + mf * 16 + (lane >> 2);
            int cc = wn * 32 + nf * 8 + (lane & 3) * 2;
            float bi0 = __ldg(b2 + cc), bi1 = __ldg(b2 + cc + 1);
            int g0 = row0 + rl, g1 = g0 + 8;
            float x00 = 0.f, x01 = 0.f, x10 = 0.f, x11 = 0.f;
            if (g0 < Nn) {
                float2 v = *(const float2*)(x + (size_t)g0 * DD + cc);
                x00 = v.x; x01 = v.y;
            }
            if (g1 < Nn) {
                float2 v = *(const float2*)(x + (size_t)g1 * DD + cc);
                x10 = v.x; x11 = v.y;
            }
            yb[rl * 129 + cc]           = acc2[mf][nf][0] + bi0 + x00;
            yb[rl * 129 + cc + 1]       = acc2[mf][nf][1] + bi1 + x01;
            yb[(rl + 8) * 129 + cc]     = acc2[mf][nf][2] + bi0 + x10;
            yb[(rl + 8) * 129 + cc + 1] = acc2[mf][nf][3] + bi1 + x11;
        }
    __syncthreads();
    if (t < 256) {
        int row = t >> 1;
        const float* r = yb + row * 129 + (t & 1) * 64;
        float s0 = 0.f, s1 = 0.f;
#pragma unroll
        for (int c = 0; c < 64; c++) { float v = r[c]; s0 += v; s1 += v * v; }
        s0 += __shfl_xor_sync(0xffffffffu, s0, 1);
        s1 += __shfl_xor_sync(0xffffffffu, s1, 1);
        if ((t & 1) == 0) {
            float mu = s0 * (1.f / 128.f);
            float var = s1 * (1.f / 128.f) - mu * mu;
            mus[row] = mu;
            rss[row] = rsqrtf(var + 1e-5f);
        }
    }
    __syncthreads();
#pragma unroll
    for (int i = 0; i < 32; i++) {
        int w = t + i * 512;
        int row = w >> 7, col = w & 127;
        int grow = row0 + row;
        if (grow < Nn) {
            float v = yb[row * 129 + col];
            out[(size_t)grow * DD + col] =
                (v - mus[row]) * rss[row] * __ldg(gamma + col) + __ldg(beta + col);
        }
    }
}

// ---------------------------------------------------------------------------
extern "C" void kernel_launch(void* const* d_in, const int* in_sizes, int n_in,
                              void* d_out, int out_size) {
    const float* x       = (const float*)d_in[0];
    const float* W1      = (const float*)d_in[1];
    const float* b1      = (const float*)d_in[2];
    const float* W2      = (const float*)d_in[3];
    const float* b2      = (const float*)d_in[4];
    const float* gamma   = (const float*)d_in[5];
    const float* beta    = (const float*)d_in[6];
    const void*  ei      = d_in[7];
    const float* ed      = (const float*)d_in[8];
    const float* degrees = (const float*)d_in[9];

    int Nn = in_sizes[0] / DD;
    int E  = in_sizes[8];

    cudaFuncSetAttribute(k_fused, cudaFuncAttributeMaxDynamicSharedMemorySize,
                         SMEM_REQ);

    int ZB = (Nn + 255) / 256;
    int XB = (Nn * DD + 255) / 256;
    int prep_blocks = 1 + ZB + (HH * KP) / 256 + (DD * HH) / 256 + XB;
    k_prep<<<prep_blocks, 256>>>(W1, W2, x, ei, E, Nn);
    k_edge<<<(E + 255) / 256, 256>>>(ei, ed, E, Nn);
    k_feat<<<(Nn + 7) / 8, 256>>>(degrees, Nn);

    int mt = (Nn + 127) / 128;  // 391
    k_fused<<<mt, 512, SMEM_REQ>>>(x, W1, b1, b2, gamma, beta, degrees,
                                   (float*)d_out, Nn);
}

// round 9
// speedup vs baseline: 4.8081x; 1.0500x over previous
#include <cuda_runtime.h>
#include <cuda_fp16.h>
#include <cstdint>

// ---------------------------------------------------------------------------
// ResidualGNNLayer (sm_103, single-term fp16 mma.sync, de-fused):
//   k_prep: detect + zero + W1/W2 fp16 transpose + x->fp16
//   k_edge: bucket edges; k_feat: warp-per-node fp16 gather-mean
//   k_gemm1: h = relu(feat@W1 + b1 + rank2(deg,md)) -> global fp16
//   k_gemm2: out = LN(x + h@W2 + b2)
//   Both GEMMs: 256 thr / 8 warps 64x32, BK=32, 3-stage cp.async, 2 CTAs/SM.
// ---------------------------------------------------------------------------

#define DD 128
#define HH 512
#define KP 256
#define CAP 128
#define NN_MAX 50048    // 391 * 128

static __device__ int   g_is64;
static __device__ int   g_cnt[NN_MAX];
static __device__ float g_dist[NN_MAX];
static __device__ int   g_slots[NN_MAX * CAP];

static __device__ __half g_xh[(size_t)NN_MAX * DD];
static __device__ __half g_feat[(size_t)NN_MAX * KP];
static __device__ __half g_h[(size_t)NN_MAX * HH];
static __device__ __half g_w1t[HH * KP];              // [n=512][k=256]
static __device__ __half g_w2t[DD * HH];              // [n=128][k=512]

// ---------------- PTX helpers ----------------------------------------------
__device__ __forceinline__ uint32_t smem_u32(const void* p) {
    uint32_t a;
    asm("{ .reg .u64 t; cvta.to.shared.u64 t, %1; cvt.u32.u64 %0, t; }"
        : "=r"(a) : "l"(p));
    return a;
}
__device__ __forceinline__ void cp16(uint32_t d, const void* s) {
    asm volatile("cp.async.ca.shared.global [%0], [%1], 16;" :: "r"(d), "l"(s));
}
#define CP_COMMIT() asm volatile("cp.async.commit_group;" ::: "memory")
#define CP_WAIT(n)  asm volatile("cp.async.wait_group %0;" :: "n"(n) : "memory")

__device__ __forceinline__ void ldm_x4(uint32_t addr, uint32_t r[4]) {
    asm volatile("ldmatrix.sync.aligned.m8n8.x4.shared.b16 {%0,%1,%2,%3}, [%4];"
                 : "=r"(r[0]), "=r"(r[1]), "=r"(r[2]), "=r"(r[3]) : "r"(addr));
}
__device__ __forceinline__ void mma16816(float d[4], const uint32_t a[4],
                                         const uint32_t b0, const uint32_t b1) {
    asm volatile(
        "mma.sync.aligned.m16n8k16.row.col.f32.f16.f16.f32 "
        "{%0,%1,%2,%3},{%4,%5,%6,%7},{%8,%9},{%0,%1,%2,%3};"
        : "+f"(d[0]), "+f"(d[1]), "+f"(d[2]), "+f"(d[3])
        : "r"(a[0]), "r"(a[1]), "r"(a[2]), "r"(a[3]), "r"(b0), "r"(b1));
}
__device__ __forceinline__ uint32_t swz(int r, int c) {
    return (uint32_t)(r * 64 + (((((c >> 4) ^ (r >> 1)) & 3) << 4) | (c & 15)));
}

// ---------------- prep ------------------------------------------------------
__global__ void k_prep(const float* __restrict__ W1, const float* __restrict__ W2,
                       const float* __restrict__ x,
                       const void* __restrict__ eraw, int E, int Nn) {
    int b = blockIdx.x, t = threadIdx.x;
    if (b == 0) {
        if (t == 0) {
            const long long* p64 = (const long long*)eraw;
            int ok64 = 1;
            int step = E / 32; if (step < 1) step = 1;
            for (int i = 0; i < 32; i++) {
                long long idx = (long long)i * step;
                if (idx >= E) break;
                long long v = p64[idx];
                if (v < 0 || v >= Nn) { ok64 = 0; break; }
            }
            g_is64 = ok64;
        }
        return;
    }
    int ZB = (Nn + 255) / 256;
    if (b - 1 < ZB) {
        int i = (b - 1) * 256 + t;
        if (i < Nn) { g_cnt[i] = 0; g_dist[i] = 0.f; }
        return;
    }
    int b2 = b - 1 - ZB;
    if (b2 < (HH * KP) / 256) {
        int idx = b2 * 256 + t;
        int n = idx >> 8, k = idx & 255;
        g_w1t[idx] = __float2half_rn(W1[k * HH + n]);
        return;
    }
    int b3 = b2 - (HH * KP) / 256;
    if (b3 < (DD * HH) / 256) {
        int idx = b3 * 256 + t;
        int n = idx >> 9, k = idx & 511;
        g_w2t[idx] = __float2half_rn(W2[k * DD + n]);
        return;
    }
    int b4 = b3 - (DD * HH) / 256;
    int idx = b4 * 256 + t;
    if (idx < Nn * DD) g_xh[idx] = __float2half_rn(x[idx]);
}

__global__ void k_edge(const void* __restrict__ eraw,
                       const float* __restrict__ ed, int E, int Nn) {
    int e = blockIdx.x * blockDim.x + threadIdx.x;
    if (e >= E) return;
    int src, dst;
    if (g_is64) {
        const long long* p = (const long long*)eraw;
        src = (int)p[e]; dst = (int)p[E + e];
    } else {
        const int* p = (const int*)eraw;
        src = p[e]; dst = p[E + e];
    }
    src = min(max(src, 0), Nn - 1);
    dst = min(max(dst, 0), Nn - 1);
    int p = atomicAdd(&g_cnt[src], 1);
    if (p < CAP) g_slots[src * CAP + p] = dst;
    atomicAdd(&g_dist[src], ed[e]);
}

__global__ void k_feat(const float* __restrict__ degrees, int Nn) {
    int gw = (blockIdx.x * blockDim.x + threadIdx.x) >> 5;
    int lane = threadIdx.x & 31;
    if (gw >= Nn) return;
    int cnt = g_cnt[gw]; if (cnt > CAP) cnt = CAP;
    const int* slots = g_slots + gw * CAP;
    float4 acc = make_float4(0.f, 0.f, 0.f, 0.f);
    int dnext = (cnt > 0) ? slots[0] : 0;
    for (int j = 0; j < cnt; j++) {
        int dcur = dnext;
        if (j + 1 < cnt) dnext = slots[j + 1];
        uint2 u = *(const uint2*)(g_xh + (size_t)dcur * DD + lane * 4);
        float2 f01 = __half22float2(*(__half2*)&u.x);
        float2 f23 = __half22float2(*(__half2*)&u.y);
        acc.x += f01.x; acc.y += f01.y; acc.z += f23.x; acc.w += f23.y;
    }
    float inv = 1.f / fmaxf(degrees[gw], 1.f);
    __half* f = g_feat + (size_t)gw * KP;
    *(uint2*)(f + lane * 4) = *(const uint2*)(g_xh + (size_t)gw * DD + lane * 4);
    *(__half2*)(f + DD + lane * 4) = __floats2half2_rn(acc.x * inv, acc.y * inv);
    *(__half2*)(f + DD + lane * 4 + 2) = __floats2half2_rn(acc.z * inv, acc.w * inv);
}

// ---------------------------------------------------------------------------
// GEMM common: CTA 128x128, 8 warps (2 wm x 4 wn) of 64x32, BK=32, 3 stages.
// Stage 16KB: A @0 (128r x 64B swizzled), B @8192.
// ---------------------------------------------------------------------------
#define STG(s) ((s) * 16384)

struct Frags {
    uint32_t Ah[4][4];
    uint32_t Bh[4][2];
};
__device__ __forceinline__ void load_frags(uint32_t sb, int wm, int wn,
                                           int lane, int ks, Frags& f) {
#pragma unroll
    for (int mf = 0; mf < 4; mf++)
        ldm_x4(sb + swz(wm * 64 + mf * 16 + (lane & 15),
                        ks * 32 + (lane >> 4) * 16), f.Ah[mf]);
#pragma unroll
    for (int p = 0; p < 2; p++) {
        uint32_t addr = sb + 8192 + swz(wn * 32 + p * 16 + (lane & 15),
                                        ks * 32 + (lane >> 4) * 16);
        uint32_t r[4];
        ldm_x4(addr, r);
        f.Bh[p * 2 + 0][0] = r[0]; f.Bh[p * 2 + 0][1] = r[2];
        f.Bh[p * 2 + 1][0] = r[1]; f.Bh[p * 2 + 1][1] = r[3];
    }
}
__device__ __forceinline__ void mma_all(float acc[4][4][4], const Frags& f) {
#pragma unroll
    for (int mf = 0; mf < 4; mf++)
#pragma unroll
        for (int nf = 0; nf < 4; nf++)
            mma16816(acc[mf][nf], f.Ah[mf], f.Bh[nf][0], f.Bh[nf][1]);
}

// ---------------------------------------------------------------------------
// GEMM1: h = relu(feat @ W1 + b1 + deg*W1[256] + md*W1[257]); K=256, 8 steps
// smem: stages 49152 + degv 512 + mdv 512 = 50176  -> 2 CTAs/SM
// ---------------------------------------------------------------------------
#define G1_SMEM 50176
__global__ __launch_bounds__(256, 2) void k_gemm1(
    const float* __restrict__ W1, const float* __restrict__ b1,
    const float* __restrict__ degrees, int Nn) {
    extern __shared__ __align__(128) char sm[];
    uint32_t base = smem_u32(sm);
    int t = threadIdx.x, lane = t & 31, wid = t >> 5;
    int wm = wid >> 2, wn = wid & 3;
    int row0 = blockIdx.x * 128, col0 = blockIdx.y * 128;

    float* degv = (float*)(sm + 49152);
    float* mdv  = (float*)(sm + 49664);
    if (t < 128) {
        int gr = row0 + t;
        float dr = (gr < Nn) ? degrees[gr] : 0.f;
        float ds = (gr < Nn) ? g_dist[gr] : 0.f;
        degv[t] = dr;
        mdv[t]  = ds / fmaxf(dr, 1.f);
    }

    float acc[4][4][4];
#pragma unroll
    for (int a = 0; a < 4; a++)
#pragma unroll
        for (int b = 0; b < 4; b++)
#pragma unroll
            for (int c = 0; c < 4; c++) acc[a][b][c] = 0.f;

    // loader: quads q = 2t, 2t+1; row = q>>2, seg = (q&3)*16 bytes
    int r0l = (2 * t) >> 2, s0l = ((2 * t) & 3) * 16;
    int r1l = (2 * t + 1) >> 2, s1l = ((2 * t + 1) & 3) * 16;
    const char* pA0 = (const char*)(g_feat + (size_t)(row0 + r0l) * KP) + s0l;
    const char* pA1 = (const char*)(g_feat + (size_t)(row0 + r1l) * KP) + s1l;
    const char* pB0 = (const char*)(g_w1t + (size_t)(col0 + r0l) * KP) + s0l;
    const char* pB1 = (const char*)(g_w1t + (size_t)(col0 + r1l) * KP) + s1l;
    uint32_t dA0 = base + swz(r0l, s0l), dA1 = base + swz(r1l, s1l);

#pragma unroll 1
    for (int s = 0; s < 2; s++) {
        cp16(dA0 + STG(s), pA0 + s * 64);
        cp16(dA1 + STG(s), pA1 + s * 64);
        cp16(dA0 + STG(s) + 8192, pB0 + s * 64);
        cp16(dA1 + STG(s) + 8192, pB1 + s * 64);
        CP_COMMIT();
    }
#pragma unroll 1
    for (int s = 0; s < 8; s++) {
        if (s < 7) { CP_WAIT(1); } else { CP_WAIT(0); }
        __syncthreads();
        if (s + 2 < 8) {
            int sp = (s + 2) % 3;
            cp16(dA0 + STG(sp), pA0 + (s + 2) * 64);
            cp16(dA1 + STG(sp), pA1 + (s + 2) * 64);
            cp16(dA0 + STG(sp) + 8192, pB0 + (s + 2) * 64);
            cp16(dA1 + STG(sp) + 8192, pB1 + (s + 2) * 64);
            CP_COMMIT();
        }
        uint32_t sb = base + STG(s % 3);
#pragma unroll
        for (int ks = 0; ks < 2; ks++) {
            Frags f;
            load_frags(sb, wm, wn, lane, ks, f);
            mma_all(acc, f);
        }
    }

    // epilogue: bias + rank2 + relu -> g_h fp16
#pragma unroll
    for (int nf = 0; nf < 4; nf++) {
        int cg = col0 + wn * 32 + nf * 8 + (lane & 3) * 2;
        float b10 = __ldg(b1 + cg), b11 = __ldg(b1 + cg + 1);
        float wd0 = __ldg(W1 + 256 * HH + cg), wd1 = __ldg(W1 + 256 * HH + cg + 1);
        float wq0 = __ldg(W1 + 257 * HH + cg), wq1 = __ldg(W1 + 257 * HH + cg + 1);
#pragma unroll
        for (int mf = 0; mf < 4; mf++) {
            int rl = wm * 64 + mf * 16 + (lane >> 2);
            float d0 = degv[rl], m0 = mdv[rl];
            float d1 = degv[rl + 8], m1 = mdv[rl + 8];
            float v00 = fmaxf(acc[mf][nf][0] + b10 + d0 * wd0 + m0 * wq0, 0.f);
            float v01 = fmaxf(acc[mf][nf][1] + b11 + d0 * wd1 + m0 * wq1, 0.f);
            float v10 = fmaxf(acc[mf][nf][2] + b10 + d1 * wd0 + m1 * wq0, 0.f);
            float v11 = fmaxf(acc[mf][nf][3] + b11 + d1 * wd1 + m1 * wq1, 0.f);
            *(__half2*)(g_h + (size_t)(row0 + rl) * HH + cg) =
                __floats2half2_rn(v00, v01);
            *(__half2*)(g_h + (size_t)(row0 + rl + 8) * HH + cg) =
                __floats2half2_rn(v10, v11);
        }
    }
}

// ---------------------------------------------------------------------------
// GEMM2 + residual + LN: out = LN(x + h@W2 + b2); K=512, 16 steps
// smem: stages 49152 + part0 2048 + part1 2048 + mus 512 + rss 512 = 54272
// ---------------------------------------------------------------------------
#define G2_SMEM 54272
__global__ __launch_bounds__(256, 2) void k_gemm2(
    const float* __restrict__ x, const float* __restrict__ b2,
    const float* __restrict__ gamma, const float* __restrict__ beta,
    float* __restrict__ out, int Nn) {
    extern __shared__ __align__(128) char sm[];
    uint32_t base = smem_u32(sm);
    int t = threadIdx.x, lane = t & 31, wid = t >> 5;
    int wm = wid >> 2, wn = wid & 3;
    int row0 = blockIdx.x * 128;
    float* part0 = (float*)(sm + 49152);   // [4 wn][128]
    float* part1 = (float*)(sm + 51200);
    float* mus   = (float*)(sm + 53248);
    float* rss   = (float*)(sm + 53760);

    float acc[4][4][4];
#pragma unroll
    for (int a = 0; a < 4; a++)
#pragma unroll
        for (int b = 0; b < 4; b++)
#pragma unroll
            for (int c = 0; c < 4; c++) acc[a][b][c] = 0.f;

    int r0l = (2 * t) >> 2, s0l = ((2 * t) & 3) * 16;
    int r1l = (2 * t + 1) >> 2, s1l = ((2 * t + 1) & 3) * 16;
    const char* pA0 = (const char*)(g_h + (size_t)(row0 + r0l) * HH) + s0l;
    const char* pA1 = (const char*)(g_h + (size_t)(row0 + r1l) * HH) + s1l;
    const char* pB0 = (const char*)(g_w2t + (size_t)r0l * HH) + s0l;
    const char* pB1 = (const char*)(g_w2t + (size_t)r1l * HH) + s1l;
    uint32_t dA0 = base + swz(r0l, s0l), dA1 = base + swz(r1l, s1l);

#pragma unroll 1
    for (int s = 0; s < 2; s++) {
        cp16(dA0 + STG(s), pA0 + s * 64);
        cp16(dA1 + STG(s), pA1 + s * 64);
        cp16(dA0 + STG(s) + 8192, pB0 + s * 64);
        cp16(dA1 + STG(s) + 8192, pB1 + s * 64);
        CP_COMMIT();
    }
#pragma unroll 1
    for (int s = 0; s < 16; s++) {
        if (s < 15) { CP_WAIT(1); } else { CP_WAIT(0); }
        __syncthreads();
        if (s + 2 < 16) {
            int sp = (s + 2) % 3;
            cp16(dA0 + STG(sp), pA0 + (s + 2) * 64);
            cp16(dA1 + STG(sp), pA1 + (s + 2) * 64);
            cp16(dA0 + STG(sp) + 8192, pB0 + (s + 2) * 64);
            cp16(dA1 + STG(sp) + 8192, pB1 + (s + 2) * 64);
            CP_COMMIT();
        }
        uint32_t sb = base + STG(s % 3);
#pragma unroll
        for (int ks = 0; ks < 2; ks++) {
            Frags f;
            load_frags(sb, wm, wn, lane, ks, f);
            mma_all(acc, f);
        }
    }

    // epilogue: y = acc + b2 + x (in regs); row stats via quad-shfl + smem
#pragma unroll
    for (int nf = 0; nf < 4; nf++) {
        int cc = wn * 32 + nf * 8 + (lane & 3) * 2;
        float b20 = __ldg(b2 + cc), b21 = __ldg(b2 + cc + 1);
#pragma unroll
        for (int mf = 0; mf < 4; mf++) {
            int g0 = row0 + wm * 64 + mf * 16 + (lane >> 2);
            float2 xv0 = make_float2(0.f, 0.f), xv1 = xv0;
            if (g0 < Nn)     xv0 = *(const float2*)(x + (size_t)g0 * DD + cc);
            if (g0 + 8 < Nn) xv1 = *(const float2*)(x + (size_t)(g0 + 8) * DD + cc);
            acc[mf][nf][0] += b20 + xv0.x;
            acc[mf][nf][1] += b21 + xv0.y;
            acc[mf][nf][2] += b20 + xv1.x;
            acc[mf][nf][3] += b21 + xv1.y;
        }
    }
#pragma unroll
    for (int mf = 0; mf < 4; mf++) {
#pragma unroll
        for (int h = 0; h < 2; h++) {
            float s0 = 0.f, s1 = 0.f;
#pragma unroll
            for (int nf = 0; nf < 4; nf++) {
                float a0 = acc[mf][nf][2 * h], a1 = acc[mf][nf][2 * h + 1];
                s0 += a0 + a1;
                s1 += a0 * a0 + a1 * a1;
            }
            s0 += __shfl_xor_sync(0xffffffffu, s0, 1);
            s1 += __shfl_xor_sync(0xffffffffu, s1, 1);
            s0 += __shfl_xor_sync(0xffffffffu, s0, 2);
            s1 += __shfl_xor_sync(0xffffffffu, s1, 2);
            if ((lane & 3) == 0) {
                int rl = wm * 64 + mf * 16 + (lane >> 2) + h * 8;
                part0[wn * 128 + rl] = s0;
                part1[wn * 128 + rl] = s1;
            }
        }
    }
    __syncthreads();
    if (t < 128) {
        float s0 = part0[t] + part0[128 + t] + part0[256 + t] + part0[384 + t];
        float s1 = part1[t] + part1[128 + t] + part1[256 + t] + part1[384 + t];
        float mu = s0 * (1.f / 128.f);
        float var = s1 * (1.f / 128.f) - mu * mu;
        mus[t] = mu;
        rss[t] = rsqrtf(var + 1e-5f);
    }
    __syncthreads();
#pragma unroll
    for (int nf = 0; nf < 4; nf++) {
        int cc = wn * 32 + nf * 8 + (lane & 3) * 2;
        float gg0 = __ldg(gamma + cc), gg1 = __ldg(gamma + cc + 1);
        float be0 = __ldg(beta + cc), be1 = __ldg(beta + cc + 1);
#pragma unroll
        for (int mf = 0; mf < 4; mf++) {
            int rl = wm * 64 + mf * 16 + (lane >> 2);
            int g0 = row0 + rl;
            if (g0 < Nn) {
                float mu = mus[rl], rs = rss[rl];
                float2 o;
                o.x = (acc[mf][nf][0] - mu) * rs * gg0 + be0;
                o.y = (acc[mf][nf][1] - mu) * rs * gg1 + be1;
                *(float2*)(out + (size_t)g0 * DD + cc) = o;
            }
            if (g0 + 8 < Nn) {
                float mu = mus[rl + 8], rs = rss[rl + 8];
                float2 o;
                o.x = (acc[mf][nf][2] - mu) * rs * gg0 + be0;
                o.y = (acc[mf][nf][3] - mu) * rs * gg1 + be1;
                *(float2*)(out + (size_t)(g0 + 8) * DD + cc) = o;
            }
        }
    }
}

// ---------------------------------------------------------------------------
extern "C" void kernel_launch(void* const* d_in, const int* in_sizes, int n_in,
                              void* d_out, int out_size) {
    const float* x       = (const float*)d_in[0];
    const float* W1      = (const float*)d_in[1];
    const float* b1      = (const float*)d_in[2];
    const float* W2      = (const float*)d_in[3];
    const float* b2      = (const float*)d_in[4];
    const float* gamma   = (const float*)d_in[5];
    const float* beta    = (const float*)d_in[6];
    const void*  ei      = d_in[7];
    const float* ed      = (const float*)d_in[8];
    const float* degrees = (const float*)d_in[9];

    int Nn = in_sizes[0] / DD;
    int E  = in_sizes[8];

    cudaFuncSetAttribute(k_gemm1, cudaFuncAttributeMaxDynamicSharedMemorySize, G1_SMEM);
    cudaFuncSetAttribute(k_gemm2, cudaFuncAttributeMaxDynamicSharedMemorySize, G2_SMEM);

    int ZB = (Nn + 255) / 256;
    int XB = (Nn * DD + 255) / 256;
    int prep_blocks = 1 + ZB + (HH * KP) / 256 + (DD * HH) / 256 + XB;
    k_prep<<<prep_blocks, 256>>>(W1, W2, x, ei, E, Nn);
    k_edge<<<(E + 255) / 256, 256>>>(ei, ed, E, Nn);
    k_feat<<<(Nn + 7) / 8, 256>>>(degrees, Nn);

    int mt = (Nn + 127) / 128;  // 391
    k_gemm1<<<dim3(mt, 4), 256, G1_SMEM>>>(W1, b1, degrees, Nn);
    k_gemm2<<<mt, 256, G2_SMEM>>>(x, b2, gamma, beta, (float*)d_out, Nn);
}

// round 10
// speedup vs baseline: 5.1349x; 1.0680x over previous
#include <cuda_runtime.h>
#include <cuda_fp16.h>
#include <cstdint>

// ---------------------------------------------------------------------------
// ResidualGNNLayer (sm_103, fp16 mma.sync, 64x64 warp tiles):
//   k_prep: detect + zero + W1/W2 fp16 transpose + x->fp16
//   k_edge: bucket edges; k_feat: warp-per-node fp16 gather-mean
//   k_gemm1: h = relu(feat@W1 + b1 + rank2(deg,md))
//   k_gemm2: out = LN(x + h@W2 + b2)
//   GEMMs: 128 thr / 4 warps (2x2) of 64x64, BK=32, 3-stage, 2 CTAs/SM.
// ---------------------------------------------------------------------------

#define DD 128
#define HH 512
#define KP 256
#define CAP 128
#define NN_MAX 50048    // 391 * 128

static __device__ int   g_is64;
static __device__ int   g_cnt[NN_MAX];
static __device__ float g_dist[NN_MAX];
static __device__ int   g_slots[NN_MAX * CAP];

static __device__ __half g_xh[(size_t)NN_MAX * DD];
static __device__ __half g_feat[(size_t)NN_MAX * KP];
static __device__ __half g_h[(size_t)NN_MAX * HH];
static __device__ __half g_w1t[HH * KP];              // [n=512][k=256]
static __device__ __half g_w2t[DD * HH];              // [n=128][k=512]

// ---------------- PTX helpers ----------------------------------------------
__device__ __forceinline__ uint32_t smem_u32(const void* p) {
    uint32_t a;
    asm("{ .reg .u64 t; cvta.to.shared.u64 t, %1; cvt.u32.u64 %0, t; }"
        : "=r"(a) : "l"(p));
    return a;
}
__device__ __forceinline__ void cp16(uint32_t d, const void* s) {
    asm volatile("cp.async.ca.shared.global [%0], [%1], 16;" :: "r"(d), "l"(s));
}
#define CP_COMMIT() asm volatile("cp.async.commit_group;" ::: "memory")
#define CP_WAIT(n)  asm volatile("cp.async.wait_group %0;" :: "n"(n) : "memory")

__device__ __forceinline__ void ldm_x4(uint32_t addr, uint32_t r[4]) {
    asm volatile("ldmatrix.sync.aligned.m8n8.x4.shared.b16 {%0,%1,%2,%3}, [%4];"
                 : "=r"(r[0]), "=r"(r[1]), "=r"(r[2]), "=r"(r[3]) : "r"(addr));
}
__device__ __forceinline__ void mma16816(float d[4], const uint32_t a[4],
                                         const uint32_t b0, const uint32_t b1) {
    asm volatile(
        "mma.sync.aligned.m16n8k16.row.col.f32.f16.f16.f32 "
        "{%0,%1,%2,%3},{%4,%5,%6,%7},{%8,%9},{%0,%1,%2,%3};"
        : "+f"(d[0]), "+f"(d[1]), "+f"(d[2]), "+f"(d[3])
        : "r"(a[0]), "r"(a[1]), "r"(a[2]), "r"(a[3]), "r"(b0), "r"(b1));
}
__device__ __forceinline__ uint32_t swz(int r, int c) {
    return (uint32_t)(r * 64 + (((((c >> 4) ^ (r >> 1)) & 3) << 4) | (c & 15)));
}

// ---------------- prep ------------------------------------------------------
__global__ void k_prep(const float* __restrict__ W1, const float* __restrict__ W2,
                       const float* __restrict__ x,
                       const void* __restrict__ eraw, int E, int Nn) {
    int b = blockIdx.x, t = threadIdx.x;
    if (b == 0) {
        if (t == 0) {
            const long long* p64 = (const long long*)eraw;
            int ok64 = 1;
            int step = E / 32; if (step < 1) step = 1;
            for (int i = 0; i < 32; i++) {
                long long idx = (long long)i * step;
                if (idx >= E) break;
                long long v = p64[idx];
                if (v < 0 || v >= Nn) { ok64 = 0; break; }
            }
            g_is64 = ok64;
        }
        return;
    }
    int ZB = (Nn + 255) / 256;
    if (b - 1 < ZB) {
        int i = (b - 1) * 256 + t;
        if (i < Nn) { g_cnt[i] = 0; g_dist[i] = 0.f; }
        return;
    }
    int b2 = b - 1 - ZB;
    if (b2 < (HH * KP) / 256) {
        int idx = b2 * 256 + t;
        int n = idx >> 8, k = idx & 255;
        g_w1t[idx] = __float2half_rn(W1[k * HH + n]);
        return;
    }
    int b3 = b2 - (HH * KP) / 256;
    if (b3 < (DD * HH) / 256) {
        int idx = b3 * 256 + t;
        int n = idx >> 9, k = idx & 511;
        g_w2t[idx] = __float2half_rn(W2[k * DD + n]);
        return;
    }
    int b4 = b3 - (DD * HH) / 256;
    int idx = b4 * 256 + t;
    if (idx < Nn * DD) g_xh[idx] = __float2half_rn(x[idx]);
}

__global__ void k_edge(const void* __restrict__ eraw,
                       const float* __restrict__ ed, int E, int Nn) {
    int e = blockIdx.x * blockDim.x + threadIdx.x;
    if (e >= E) return;
    int src, dst;
    if (g_is64) {
        const long long* p = (const long long*)eraw;
        src = (int)p[e]; dst = (int)p[E + e];
    } else {
        const int* p = (const int*)eraw;
        src = p[e]; dst = p[E + e];
    }
    src = min(max(src, 0), Nn - 1);
    dst = min(max(dst, 0), Nn - 1);
    int p = atomicAdd(&g_cnt[src], 1);
    if (p < CAP) g_slots[src * CAP + p] = dst;
    atomicAdd(&g_dist[src], ed[e]);
}

__global__ void k_feat(const float* __restrict__ degrees, int Nn) {
    int gw = (blockIdx.x * blockDim.x + threadIdx.x) >> 5;
    int lane = threadIdx.x & 31;
    if (gw >= Nn) return;
    int cnt = g_cnt[gw]; if (cnt > CAP) cnt = CAP;
    const int* slots = g_slots + gw * CAP;
    float4 acc = make_float4(0.f, 0.f, 0.f, 0.f);
    int dnext = (cnt > 0) ? slots[0] : 0;
    for (int j = 0; j < cnt; j++) {
        int dcur = dnext;
        if (j + 1 < cnt) dnext = slots[j + 1];
        uint2 u = *(const uint2*)(g_xh + (size_t)dcur * DD + lane * 4);
        float2 f01 = __half22float2(*(__half2*)&u.x);
        float2 f23 = __half22float2(*(__half2*)&u.y);
        acc.x += f01.x; acc.y += f01.y; acc.z += f23.x; acc.w += f23.y;
    }
    float inv = 1.f / fmaxf(degrees[gw], 1.f);
    __half* f = g_feat + (size_t)gw * KP;
    *(uint2*)(f + lane * 4) = *(const uint2*)(g_xh + (size_t)gw * DD + lane * 4);
    *(__half2*)(f + DD + lane * 4) = __floats2half2_rn(acc.x * inv, acc.y * inv);
    *(__half2*)(f + DD + lane * 4 + 2) = __floats2half2_rn(acc.z * inv, acc.w * inv);
}

// ---------------------------------------------------------------------------
// GEMM common: CTA 128x128, 4 warps (2x2) of 64x64, BK=32, 3 stages.
// Stage 16KB: A @0 (128r x 64B swizzled), B @8192 (128r x 64B).
// ---------------------------------------------------------------------------
#define STG(s) ((s) * 16384)

struct Frag64 {
    uint32_t Ah[4][4];
    uint32_t Bh[8][2];
};
__device__ __forceinline__ void load_frags64(uint32_t sb, int wm, int wn,
                                             int lane, int ks, Frag64& f) {
#pragma unroll
    for (int mf = 0; mf < 4; mf++)
        ldm_x4(sb + swz(wm * 64 + mf * 16 + (lane & 15),
                        ks * 32 + (lane >> 4) * 16), f.Ah[mf]);
#pragma unroll
    for (int p = 0; p < 4; p++) {
        uint32_t addr = sb + 8192 + swz(wn * 64 + p * 16 + (lane & 15),
                                        ks * 32 + (lane >> 4) * 16);
        uint32_t r[4];
        ldm_x4(addr, r);
        f.Bh[p * 2 + 0][0] = r[0]; f.Bh[p * 2 + 0][1] = r[2];
        f.Bh[p * 2 + 1][0] = r[1]; f.Bh[p * 2 + 1][1] = r[3];
    }
}
__device__ __forceinline__ void mma_all64(float acc[4][8][4], const Frag64& f) {
#pragma unroll
    for (int mf = 0; mf < 4; mf++)
#pragma unroll
        for (int nf = 0; nf < 8; nf++)
            mma16816(acc[mf][nf], f.Ah[mf], f.Bh[nf][0], f.Bh[nf][1]);
}

// ---------------------------------------------------------------------------
// GEMM1: h = relu(feat @ W1 + b1 + deg*W1[256] + md*W1[257]); K=256, 8 steps
// smem: 49152 stages + degv 512 + mdv 512 = 50176 -> 2 CTAs/SM
// ---------------------------------------------------------------------------
#define G1_SMEM 50176
__global__ __launch_bounds__(128, 2) void k_gemm1(
    const float* __restrict__ W1, const float* __restrict__ b1,
    const float* __restrict__ degrees, int Nn) {
    extern __shared__ __align__(128) char sm[];
    uint32_t base = smem_u32(sm);
    int t = threadIdx.x, lane = t & 31, wid = t >> 5;
    int wm = wid >> 1, wn = wid & 1;
    int row0 = blockIdx.x * 128, col0 = blockIdx.y * 128;

    float* degv = (float*)(sm + 49152);
    float* mdv  = (float*)(sm + 49664);
    {
        int gr = row0 + t;
        float dr = (gr < Nn) ? degrees[gr] : 0.f;
        float ds = (gr < Nn) ? g_dist[gr] : 0.f;
        degv[t] = dr;
        mdv[t]  = ds / fmaxf(dr, 1.f);
    }

    float acc[4][8][4];
#pragma unroll
    for (int a = 0; a < 4; a++)
#pragma unroll
        for (int b = 0; b < 8; b++)
#pragma unroll
            for (int c = 0; c < 4; c++) acc[a][b][c] = 0.f;

    // loader: 4 A quads + 4 B quads per thread; rows t>>2 + 32i, seg (t&3)*16
    int lr = t >> 2, seg = (t & 3) * 16;
    const char* pA = (const char*)(g_feat + (size_t)(row0 + lr) * KP) + seg;
    const char* pB = (const char*)(g_w1t + (size_t)(col0 + lr) * KP) + seg;
    uint32_t dA = base + swz(lr, seg);
    const int ARB = KP * 2 * 32;   // 32 rows of A source = 16384 B
    const int BRB = KP * 2 * 32;

#pragma unroll 1
    for (int s = 0; s < 2; s++) {
#pragma unroll
        for (int i = 0; i < 4; i++) {
            cp16(dA + STG(s) + 2048 * i, pA + i * ARB + s * 64);
            cp16(dA + STG(s) + 8192 + 2048 * i, pB + i * BRB + s * 64);
        }
        CP_COMMIT();
    }
#pragma unroll 1
    for (int s = 0; s < 8; s++) {
        if (s < 7) { CP_WAIT(1); } else { CP_WAIT(0); }
        __syncthreads();
        if (s + 2 < 8) {
            int sp = (s + 2) % 3;
#pragma unroll
            for (int i = 0; i < 4; i++) {
                cp16(dA + STG(sp) + 2048 * i, pA + i * ARB + (s + 2) * 64);
                cp16(dA + STG(sp) + 8192 + 2048 * i, pB + i * BRB + (s + 2) * 64);
            }
            CP_COMMIT();
        }
        uint32_t sb = base + STG(s % 3);
#pragma unroll
        for (int ks = 0; ks < 2; ks++) {
            Frag64 f;
            load_frags64(sb, wm, wn, lane, ks, f);
            mma_all64(acc, f);
        }
    }

    // epilogue: bias + rank2 + relu -> g_h fp16
#pragma unroll
    for (int nf = 0; nf < 8; nf++) {
        int cg = col0 + wn * 64 + nf * 8 + (lane & 3) * 2;
        float b10 = __ldg(b1 + cg), b11 = __ldg(b1 + cg + 1);
        float wd0 = __ldg(W1 + 256 * HH + cg), wd1 = __ldg(W1 + 256 * HH + cg + 1);
        float wq0 = __ldg(W1 + 257 * HH + cg), wq1 = __ldg(W1 + 257 * HH + cg + 1);
#pragma unroll
        for (int mf = 0; mf < 4; mf++) {
            int rl = wm * 64 + mf * 16 + (lane >> 2);
            float d0 = degv[rl], m0 = mdv[rl];
            float d1 = degv[rl + 8], m1 = mdv[rl + 8];
            float v00 = fmaxf(acc[mf][nf][0] + b10 + d0 * wd0 + m0 * wq0, 0.f);
            float v01 = fmaxf(acc[mf][nf][1] + b11 + d0 * wd1 + m0 * wq1, 0.f);
            float v10 = fmaxf(acc[mf][nf][2] + b10 + d1 * wd0 + m1 * wq0, 0.f);
            float v11 = fmaxf(acc[mf][nf][3] + b11 + d1 * wd1 + m1 * wq1, 0.f);
            *(__half2*)(g_h + (size_t)(row0 + rl) * HH + cg) =
                __floats2half2_rn(v00, v01);
            *(__half2*)(g_h + (size_t)(row0 + rl + 8) * HH + cg) =
                __floats2half2_rn(v10, v11);
        }
    }
}

// ---------------------------------------------------------------------------
// GEMM2 + residual + LN: out = LN(x + h@W2 + b2); K=512, 16 steps
// smem: 49152 stages + part0 1024 + part1 1024 + mus 512 + rss 512 = 52224
// ---------------------------------------------------------------------------
#define G2_SMEM 52224
__global__ __launch_bounds__(128, 2) void k_gemm2(
    const float* __restrict__ x, const float* __restrict__ b2,
    const float* __restrict__ gamma, const float* __restrict__ beta,
    float* __restrict__ out, int Nn) {
    extern __shared__ __align__(128) char sm[];
    uint32_t base = smem_u32(sm);
    int t = threadIdx.x, lane = t & 31, wid = t >> 5;
    int wm = wid >> 1, wn = wid & 1;
    int row0 = blockIdx.x * 128;
    float* part0 = (float*)(sm + 49152);   // [2 wn][128]
    float* part1 = (float*)(sm + 50176);
    float* mus   = (float*)(sm + 51200);
    float* rss   = (float*)(sm + 51712);

    float acc[4][8][4];
#pragma unroll
    for (int a = 0; a < 4; a++)
#pragma unroll
        for (int b = 0; b < 8; b++)
#pragma unroll
            for (int c = 0; c < 4; c++) acc[a][b][c] = 0.f;

    int lr = t >> 2, seg = (t & 3) * 16;
    const char* pA = (const char*)(g_h + (size_t)(row0 + lr) * HH) + seg;
    const char* pB = (const char*)(g_w2t + (size_t)lr * HH) + seg;
    uint32_t dA = base + swz(lr, seg);
    const int ARB = HH * 2 * 32;   // 32 rows of source = 32768 B
    const int BRB = HH * 2 * 32;

#pragma unroll 1
    for (int s = 0; s < 2; s++) {
#pragma unroll
        for (int i = 0; i < 4; i++) {
            cp16(dA + STG(s) + 2048 * i, pA + i * ARB + s * 64);
            cp16(dA + STG(s) + 8192 + 2048 * i, pB + i * BRB + s * 64);
        }
        CP_COMMIT();
    }
#pragma unroll 1
    for (int s = 0; s < 16; s++) {
        if (s < 15) { CP_WAIT(1); } else { CP_WAIT(0); }
        __syncthreads();
        if (s + 2 < 16) {
            int sp = (s + 2) % 3;
#pragma unroll
            for (int i = 0; i < 4; i++) {
                cp16(dA + STG(sp) + 2048 * i, pA + i * ARB + (s + 2) * 64);
                cp16(dA + STG(sp) + 8192 + 2048 * i, pB + i * BRB + (s + 2) * 64);
            }
            CP_COMMIT();
        }
        uint32_t sb = base + STG(s % 3);
#pragma unroll
        for (int ks = 0; ks < 2; ks++) {
            Frag64 f;
            load_frags64(sb, wm, wn, lane, ks, f);
            mma_all64(acc, f);
        }
    }

    // epilogue: y = acc + b2 + x in regs; row stats via quad-shfl + smem
#pragma unroll
    for (int nf = 0; nf < 8; nf++) {
        int cc = wn * 64 + nf * 8 + (lane & 3) * 2;
        float b20 = __ldg(b2 + cc), b21 = __ldg(b2 + cc + 1);
#pragma unroll
        for (int mf = 0; mf < 4; mf++) {
            int g0 = row0 + wm * 64 + mf * 16 + (lane >> 2);
            float2 xv0 = make_float2(0.f, 0.f), xv1 = xv0;
            if (g0 < Nn)     xv0 = *(const float2*)(x + (size_t)g0 * DD + cc);
            if (g0 + 8 < Nn) xv1 = *(const float2*)(x + (size_t)(g0 + 8) * DD + cc);
            acc[mf][nf][0] += b20 + xv0.x;
            acc[mf][nf][1] += b21 + xv0.y;
            acc[mf][nf][2] += b20 + xv1.x;
            acc[mf][nf][3] += b21 + xv1.y;
        }
    }
#pragma unroll
    for (int mf = 0; mf < 4; mf++) {
#pragma unroll
        for (int h = 0; h < 2; h++) {
            float s0 = 0.f, s1 = 0.f;
#pragma unroll
            for (int nf = 0; nf < 8; nf++) {
                float a0 = acc[mf][nf][2 * h], a1 = acc[mf][nf][2 * h + 1];
                s0 += a0 + a1;
                s1 += a0 * a0 + a1 * a1;
            }
            s0 += __shfl_xor_sync(0xffffffffu, s0, 1);
            s1 += __shfl_xor_sync(0xffffffffu, s1, 1);
            s0 += __shfl_xor_sync(0xffffffffu, s0, 2);
            s1 += __shfl_xor_sync(0xffffffffu, s1, 2);
            if ((lane & 3) == 0) {
                int rl = wm * 64 + mf * 16 + (lane >> 2) + h * 8;
                part0[wn * 128 + rl] = s0;
                part1[wn * 128 + rl] = s1;
            }
        }
    }
    __syncthreads();
    {
        float s0 = part0[t] + part0[128 + t];
        float s1 = part1[t] + part1[128 + t];
        float mu = s0 * (1.f / 128.f);
        float var = s1 * (1.f / 128.f) - mu * mu;
        mus[t] = mu;
        rss[t] = rsqrtf(var + 1e-5f);
    }
    __syncthreads();
#pragma unroll
    for (int nf = 0; nf < 8; nf++) {
        int cc = wn * 64 + nf * 8 + (lane & 3) * 2;
        float gg0 = __ldg(gamma + cc), gg1 = __ldg(gamma + cc + 1);
        float be0 = __ldg(beta + cc), be1 = __ldg(beta + cc + 1);
#pragma unroll
        for (int mf = 0; mf < 4; mf++) {
            int rl = wm * 64 + mf * 16 + (lane >> 2);
            int g0 = row0 + rl;
            if (g0 < Nn) {
                float mu = mus[rl], rs = rss[rl];
                float2 o;
                o.x = (acc[mf][nf][0] - mu) * rs * gg0 + be0;
                o.y = (acc[mf][nf][1] - mu) * rs * gg1 + be1;
                *(float2*)(out + (size_t)g0 * DD + cc) = o;
            }
            if (g0 + 8 < Nn) {
                float mu = mus[rl + 8], rs = rss[rl + 8];
                float2 o;
                o.x = (acc[mf][nf][2] - mu) * rs * gg0 + be0;
                o.y = (acc[mf][nf][3] - mu) * rs * gg1 + be1;
                *(float2*)(out + (size_t)(g0 + 8) * DD + cc) = o;
            }
        }
    }
}

// ---------------------------------------------------------------------------
extern "C" void kernel_launch(void* const* d_in, const int* in_sizes, int n_in,
                              void* d_out, int out_size) {
    const float* x       = (const float*)d_in[0];
    const float* W1      = (const float*)d_in[1];
    const float* b1      = (const float*)d_in[2];
    const float* W2      = (const float*)d_in[3];
    const float* b2      = (const float*)d_in[4];
    const float* gamma   = (const float*)d_in[5];
    const float* beta    = (const float*)d_in[6];
    const void*  ei      = d_in[7];
    const float* ed      = (const float*)d_in[8];
    const float* degrees = (const float*)d_in[9];

    int Nn = in_sizes[0] / DD;
    int E  = in_sizes[8];

    cudaFuncSetAttribute(k_gemm1, cudaFuncAttributeMaxDynamicSharedMemorySize, G1_SMEM);
    cudaFuncSetAttribute(k_gemm2, cudaFuncAttributeMaxDynamicSharedMemorySize, G2_SMEM);

    int ZB = (Nn + 255) / 256;
    int XB = (Nn * DD + 255) / 256;
    int prep_blocks = 1 + ZB + (HH * KP) / 256 + (DD * HH) / 256 + XB;
    k_prep<<<prep_blocks, 256>>>(W1, W2, x, ei, E, Nn);
    k_edge<<<(E + 255) / 256, 256>>>(ei, ed, E, Nn);
    k_feat<<<(Nn + 7) / 8, 256>>>(degrees, Nn);

    int mt = (Nn + 127) / 128;  // 391
    k_gemm1<<<dim3(mt, 4), 128, G1_SMEM>>>(W1, b1, degrees, Nn);
    k_gemm2<<<mt, 128, G2_SMEM>>>(x, b2, gamma, beta, (float*)d_out, Nn);
}